// round 1
// baseline (speedup 1.0000x reference)
#include <cuda_runtime.h>
#include <math.h>

#define ROWS 200704   // 4096 * 49
#define DM   384
#define NWIN 4096
#define NH   12
#define NTOK 49
#define HD   32

// SCALE = 32^-5 (faithful to reference code)
#define SCALE_F 2.9802322387695312e-08f

// Scratch (allocation-free rule: __device__ globals)
__device__ float g_q[(size_t)ROWS * DM];
__device__ float g_k[(size_t)ROWS * DM];
__device__ float g_v[(size_t)ROWS * DM];
__device__ float g_attn[(size_t)ROWS * DM];

// ---------------------------------------------------------------------------
// GEMM: C = A[M=200704, K=384] @ W[384, 384] + bias
// LAYOUT 0: C row-major [row*384 + col]
// LAYOUT 1: head-split  [((b*12 + h)*49 + n)*32 + d]  (b=row/49, n=row%49,
//                                                      h=col/32, d=col%32)
// 128x128 block tile, BK=8, 256 threads, 8x8 per-thread microtile.
// M=200704=128*1568, N=384=128*3, K=384=8*48 -> no bounds checks needed.
// ---------------------------------------------------------------------------
template <int LAYOUT>
__global__ __launch_bounds__(256)
void gemm384(const float* __restrict__ A, const float* __restrict__ W,
             const float* __restrict__ bias, float* __restrict__ C) {
    __shared__ float As[8][128];
    __shared__ float Bs[8][128];

    const int tid  = threadIdx.x;
    const int brow = blockIdx.y * 128;
    const int bcol = blockIdx.x * 128;
    const int tx = tid & 15;        // 0..15 -> 8 cols each
    const int ty = tid >> 4;        // 0..15 -> 8 rows each

    const int a_row = tid >> 1;           // 0..127
    const int a_col = (tid & 1) << 2;     // 0 or 4
    const int b_row = tid >> 5;           // 0..7
    const int b_col = (tid & 31) << 2;    // 0..124

    float acc[8][8];
#pragma unroll
    for (int i = 0; i < 8; i++)
#pragma unroll
        for (int j = 0; j < 8; j++) acc[i][j] = 0.f;

    const float* Ap = A + (size_t)(brow + a_row) * DM + a_col;
    const float* Wp = W + (size_t)b_row * DM + bcol + b_col;

    for (int k0 = 0; k0 < DM; k0 += 8) {
        float4 av = *(const float4*)(Ap + k0);
        As[a_col + 0][a_row] = av.x;
        As[a_col + 1][a_row] = av.y;
        As[a_col + 2][a_row] = av.z;
        As[a_col + 3][a_row] = av.w;
        float4 bv = *(const float4*)(Wp + (size_t)k0 * DM);
        *(float4*)&Bs[b_row][b_col] = bv;
        __syncthreads();

#pragma unroll
        for (int k = 0; k < 8; k++) {
            float ar[8], br[8];
            *(float4*)&ar[0] = *(const float4*)&As[k][ty * 8];
            *(float4*)&ar[4] = *(const float4*)&As[k][ty * 8 + 4];
            *(float4*)&br[0] = *(const float4*)&Bs[k][tx * 8];
            *(float4*)&br[4] = *(const float4*)&Bs[k][tx * 8 + 4];
#pragma unroll
            for (int i = 0; i < 8; i++)
#pragma unroll
                for (int j = 0; j < 8; j++)
                    acc[i][j] += ar[i] * br[j];
        }
        __syncthreads();
    }

#pragma unroll
    for (int i = 0; i < 8; i++) {
        const int row = brow + ty * 8 + i;
        const int bb = row / NTOK;
        const int nn = row - bb * NTOK;
#pragma unroll
        for (int j = 0; j < 8; j++) {
            const int col = bcol + tx * 8 + j;
            const float val = acc[i][j] + bias[col];
            if (LAYOUT == 0) {
                C[(size_t)row * DM + col] = val;
            } else {
                const int hh = col >> 5;
                const int dd = col & 31;
                C[((((size_t)bb * NH + hh) * NTOK) + nn) * HD + dd] = val;
            }
        }
    }
}

// ---------------------------------------------------------------------------
// Attention: one CTA per (window b, head h).
// q,k,v tiles [49,32] in smem; scores 49x49; row softmax; O = W @ V.
// Output written to g_attn in [row=b*49+n, col=h*32+d] row-major layout so the
// projection GEMM reads it directly.
// ---------------------------------------------------------------------------
__global__ __launch_bounds__(256)
void attn49(const float* __restrict__ q, const float* __restrict__ k,
            const float* __restrict__ v, const float* __restrict__ mask,
            float* __restrict__ out) {
    const int b = blockIdx.x;
    const int h = blockIdx.y;
    const int tid = threadIdx.x;

    __shared__ float qs[NTOK][HD + 1];
    __shared__ float ks[NTOK][HD + 1];
    __shared__ float vs[NTOK][HD];
    __shared__ float sc[NTOK][52];

    const size_t base = (((size_t)b * NH + h) * NTOK) * HD;
    const float* qp = q + base;
    const float* kp = k + base;
    const float* vp = v + base;

    for (int i = tid; i < NTOK * HD; i += 256) {
        const int r = i >> 5, c = i & 31;
        qs[r][c] = qp[i];
        ks[r][c] = kp[i];
        vs[r][c] = vp[i];
    }
    __syncthreads();

    // scores[i][j] = (q_i . k_j) * SCALE + mask[b,0,i,j]
    const float* mp = mask + ((size_t)b * NTOK) * NTOK;
    for (int idx = tid; idx < NTOK * NTOK; idx += 256) {
        const int i = idx / NTOK;
        const int j = idx - i * NTOK;
        float s = 0.f;
#pragma unroll
        for (int d = 0; d < HD; d++) s += qs[i][d] * ks[j][d];
        sc[i][j] = s * SCALE_F + mp[idx];
    }
    __syncthreads();

    // row softmax: one warp per row
    const int warp = tid >> 5, lane = tid & 31;
    for (int r = warp; r < NTOK; r += 8) {
        float e0 = sc[r][lane];
        float e1 = (lane + 32 < NTOK) ? sc[r][lane + 32] : -3.4e38f;
        float m = fmaxf(e0, e1);
#pragma unroll
        for (int off = 16; off > 0; off >>= 1)
            m = fmaxf(m, __shfl_xor_sync(0xFFFFFFFFu, m, off));
        float x0 = __expf(e0 - m);
        float x1 = (lane + 32 < NTOK) ? __expf(e1 - m) : 0.f;
        float s = x0 + x1;
#pragma unroll
        for (int off = 16; off > 0; off >>= 1)
            s += __shfl_xor_sync(0xFFFFFFFFu, s, off);
        const float inv = 1.f / s;
        sc[r][lane] = x0 * inv;
        if (lane + 32 < NTOK) sc[r][lane + 32] = x1 * inv;
    }
    __syncthreads();

    // O[i][d] = sum_j w[i][j] * v[j][d], write to [b*49+i, h*32+d] row-major
    float* op = out + ((size_t)b * NTOK) * DM + h * HD;
    for (int idx = tid; idx < NTOK * HD; idx += 256) {
        const int i = idx >> 5, d = idx & 31;
        float acc = 0.f;
#pragma unroll
        for (int j = 0; j < NTOK; j++) acc += sc[i][j] * vs[j][d];
        op[(size_t)i * DM + d] = acc;
    }
}

// ---------------------------------------------------------------------------
extern "C" void kernel_launch(void* const* d_in, const int* in_sizes, int n_in,
                              void* d_out, int out_size) {
    const float* x    = (const float*)d_in[0];
    const float* mask = (const float*)d_in[1];
    const float* Wq   = (const float*)d_in[2];
    const float* bq   = (const float*)d_in[3];
    const float* Wk   = (const float*)d_in[4];
    const float* bk   = (const float*)d_in[5];
    const float* Wv   = (const float*)d_in[6];
    const float* bv   = (const float*)d_in[7];
    const float* Wp   = (const float*)d_in[8];
    const float* bp   = (const float*)d_in[9];

    float *qp, *kp, *vp, *ap;
    cudaGetSymbolAddress((void**)&qp, g_q);
    cudaGetSymbolAddress((void**)&kp, g_k);
    cudaGetSymbolAddress((void**)&vp, g_v);
    cudaGetSymbolAddress((void**)&ap, g_attn);

    dim3 ggrid(3, ROWS / 128);   // (N tiles, M tiles)
    gemm384<1><<<ggrid, 256>>>(x, Wq, bq, qp);
    gemm384<1><<<ggrid, 256>>>(x, Wk, bk, kp);
    gemm384<1><<<ggrid, 256>>>(x, Wv, bv, vp);

    dim3 agrid(NWIN, NH);
    attn49<<<agrid, 256>>>(qp, kp, vp, mask, ap);

    gemm384<0><<<ggrid, 256>>>(ap, Wp, bp, (float*)d_out);
}

// round 3
// speedup vs baseline: 3.0634x; 3.0634x over previous
#include <cuda_runtime.h>
#include <cuda_bf16.h>
#include <cstdint>
#include <math.h>

#define ROWS 200704   // 4096 * 49
#define DM   384
#define NWIN 4096
#define NH   12
#define NTOK 49
#define HD   32

// SCALE = 32^-5 (faithful to reference code)
#define SCALE_F 2.9802322387695312e-08f

// ---------------------------------------------------------------------------
// Scratch (__device__ globals; no allocation allowed)
// ---------------------------------------------------------------------------
__device__ float g_q[(size_t)ROWS * DM];
__device__ float g_k[(size_t)ROWS * DM];
__device__ float g_v[(size_t)ROWS * DM];
__device__ float g_attn[(size_t)ROWS * DM];
// W^T as bf16 hi/lo, 4 matrices: [m][n][k]
__device__ __nv_bfloat16 g_wth[4 * 384 * 384];
__device__ __nv_bfloat16 g_wtl[4 * 384 * 384];

// ---------------------------------------------------------------------------
__device__ __forceinline__ uint32_t smem_u32(const void* p) {
    uint32_t a;
    asm("{ .reg .u64 t; cvta.to.shared.u64 t, %1; cvt.u32.u64 %0, t; }" : "=r"(a) : "l"(p));
    return a;
}

__device__ __forceinline__ void ldsm4(uint32_t& r0, uint32_t& r1, uint32_t& r2, uint32_t& r3,
                                      uint32_t addr) {
    asm volatile("ldmatrix.sync.aligned.m8n8.x4.shared.b16 {%0,%1,%2,%3}, [%4];"
                 : "=r"(r0), "=r"(r1), "=r"(r2), "=r"(r3) : "r"(addr));
}

__device__ __forceinline__ void mma16816(float* d, const uint32_t* a, const uint32_t* b) {
    asm volatile("mma.sync.aligned.m16n8k16.row.col.f32.bf16.bf16.f32 "
                 "{%0,%1,%2,%3}, {%4,%5,%6,%7}, {%8,%9}, {%0,%1,%2,%3};"
                 : "+f"(d[0]), "+f"(d[1]), "+f"(d[2]), "+f"(d[3])
                 : "r"(a[0]), "r"(a[1]), "r"(a[2]), "r"(a[3]), "r"(b[0]), "r"(b[1]));
}

__device__ __forceinline__ uint32_t pack2(float a, float b) {
    __nv_bfloat16 x = __float2bfloat16(a);
    __nv_bfloat16 y = __float2bfloat16(b);
    return (uint32_t)__bfloat16_as_ushort(x) | ((uint32_t)__bfloat16_as_ushort(y) << 16);
}
__device__ __forceinline__ void split_pack(float a, float b, uint32_t& hi, uint32_t& lo) {
    __nv_bfloat16 ah = __float2bfloat16(a);
    __nv_bfloat16 bh = __float2bfloat16(b);
    hi = (uint32_t)__bfloat16_as_ushort(ah) | ((uint32_t)__bfloat16_as_ushort(bh) << 16);
    lo = pack2(a - __bfloat162float(ah), b - __bfloat162float(bh));
}

// ---------------------------------------------------------------------------
// Weight transpose + bf16 hi/lo split: Wt[m][n][k] = W_m[k][n]
// ---------------------------------------------------------------------------
__global__ void convW(const float* __restrict__ Wq, const float* __restrict__ Wk,
                      const float* __restrict__ Wv, const float* __restrict__ Wp,
                      __nv_bfloat16* __restrict__ th, __nv_bfloat16* __restrict__ tl) {
    int idx = blockIdx.x * 256 + threadIdx.x;
    if (idx >= 4 * 384 * 384) return;
    int m = idx / (384 * 384);
    int rem = idx - m * 384 * 384;
    int n = rem / 384, k = rem - (rem / 384) * 384;
    const float* W = (m == 0) ? Wq : (m == 1) ? Wk : (m == 2) ? Wv : Wp;
    float a = W[k * 384 + n];
    __nv_bfloat16 h = __float2bfloat16(a);
    th[idx] = h;
    tl[idx] = __float2bfloat16(a - __bfloat162float(h));
}

// ---------------------------------------------------------------------------
// HMMA GEMM: C[200704, 384] = A @ W + bias.
// SPLIT=1: 3-term bf16 split (Ah*Bh + Ah*Bl + Al*Bh). SPLIT=0: plain bf16.
// CTA 128x128, BK=32, 256 threads (8 warps, 2x4 M-N), warp tile 64x32.
// LAYOUT 0: row-major out. LAYOUT 1: head-split [b,h,n,d].
// ---------------------------------------------------------------------------
#define LDAB 40   // bf16 elems per smem row (80B) -> conflict-free ldmatrix

template <int SPLIT, int LAYOUT>
__global__ __launch_bounds__(256)
void gemm_hmma(const float* __restrict__ A,
               const __nv_bfloat16* __restrict__ wth,
               const __nv_bfloat16* __restrict__ wtl,
               const float* __restrict__ bias,
               float* __restrict__ C) {
    __shared__ __nv_bfloat16 sAh[128 * LDAB];
    __shared__ __nv_bfloat16 sBh[128 * LDAB];
    __shared__ __nv_bfloat16 sAl[128 * LDAB];
    __shared__ __nv_bfloat16 sBl[128 * LDAB];

    const int tid = threadIdx.x;
    const int wid = tid >> 5, lane = tid & 31;
    const int warp_m = wid & 1;      // 0..1 -> 64-row slab
    const int warp_n = wid >> 1;     // 0..3 -> 32-col slab
    const int brow = blockIdx.y * 128;
    const int bcol = blockIdx.x * 128;

    float acc[4][4][4];
#pragma unroll
    for (int i = 0; i < 4; i++)
#pragma unroll
        for (int j = 0; j < 4; j++)
#pragma unroll
            for (int c = 0; c < 4; c++) acc[i][j][c] = 0.f;

    const uint32_t aAh = smem_u32(sAh), aBh = smem_u32(sBh);
    const uint32_t aAl = smem_u32(sAl), aBl = smem_u32(sBl);

    // staging addresses (bytes): thread covers row=tid/2, k-half=(tid&1)*16
    const uint32_t wr = (tid >> 1) * (LDAB * 2) + (tid & 1) * 32;
    const float* ap = A + (size_t)(brow + (tid >> 1)) * DM + (tid & 1) * 16;
    const __nv_bfloat16* bhp = wth + (size_t)(bcol + (tid >> 1)) * DM + (tid & 1) * 16;
    const __nv_bfloat16* blp = wtl + (size_t)(bcol + (tid >> 1)) * DM + (tid & 1) * 16;

    // ldmatrix lane address offsets (bytes)
    const uint32_t a_off = (warp_m * 64 + (lane & 7) + ((lane >> 3) & 1) * 8) * (LDAB * 2)
                         + ((lane >> 4) & 1) * 16;
    const uint32_t b_off = (warp_n * 32 + (lane & 7) + ((lane >> 4) & 1) * 8) * (LDAB * 2)
                         + ((lane >> 3) & 1) * 16;

    for (int kc = 0; kc < 12; kc++) {
        const int koff = kc * 32;
        // stage A (fp32 -> bf16 hi/lo)
        {
            float4 x0 = *(const float4*)(ap + koff);
            float4 x1 = *(const float4*)(ap + koff + 4);
            float4 x2 = *(const float4*)(ap + koff + 8);
            float4 x3 = *(const float4*)(ap + koff + 12);
            uint4 h0, l0, h1, l1;
            split_pack(x0.x, x0.y, h0.x, l0.x);
            split_pack(x0.z, x0.w, h0.y, l0.y);
            split_pack(x1.x, x1.y, h0.z, l0.z);
            split_pack(x1.z, x1.w, h0.w, l0.w);
            split_pack(x2.x, x2.y, h1.x, l1.x);
            split_pack(x2.z, x2.w, h1.y, l1.y);
            split_pack(x3.x, x3.y, h1.z, l1.z);
            split_pack(x3.z, x3.w, h1.w, l1.w);
            *(uint4*)((char*)sAh + wr) = h0;
            *(uint4*)((char*)sAh + wr + 16) = h1;
            if (SPLIT) {
                *(uint4*)((char*)sAl + wr) = l0;
                *(uint4*)((char*)sAl + wr + 16) = l1;
            }
        }
        // stage B (bf16 hi, and lo when split)
        {
            *(uint4*)((char*)sBh + wr) = *(const uint4*)(bhp + koff);
            *(uint4*)((char*)sBh + wr + 16) = *(const uint4*)(bhp + koff + 8);
            if (SPLIT) {
                *(uint4*)((char*)sBl + wr) = *(const uint4*)(blp + koff);
                *(uint4*)((char*)sBl + wr + 16) = *(const uint4*)(blp + koff + 8);
            }
        }
        __syncthreads();

#pragma unroll
        for (int s = 0; s < 2; s++) {
            const uint32_t so = s * 32;   // k16-step byte offset
            uint32_t ah[4][4], al[4][4], bh[4][2], bl[4][2];
#pragma unroll
            for (int mt = 0; mt < 4; mt++)
                ldsm4(ah[mt][0], ah[mt][1], ah[mt][2], ah[mt][3],
                      aAh + a_off + mt * 16 * (LDAB * 2) + so);
#pragma unroll
            for (int p = 0; p < 2; p++)
                ldsm4(bh[2 * p][0], bh[2 * p][1], bh[2 * p + 1][0], bh[2 * p + 1][1],
                      aBh + b_off + p * 16 * (LDAB * 2) + so);
            if (SPLIT) {
#pragma unroll
                for (int mt = 0; mt < 4; mt++)
                    ldsm4(al[mt][0], al[mt][1], al[mt][2], al[mt][3],
                          aAl + a_off + mt * 16 * (LDAB * 2) + so);
#pragma unroll
                for (int p = 0; p < 2; p++)
                    ldsm4(bl[2 * p][0], bl[2 * p][1], bl[2 * p + 1][0], bl[2 * p + 1][1],
                          aBl + b_off + p * 16 * (LDAB * 2) + so);
            }
#pragma unroll
            for (int mt = 0; mt < 4; mt++)
#pragma unroll
                for (int nt = 0; nt < 4; nt++) {
                    mma16816(acc[mt][nt], ah[mt], bh[nt]);
                    if (SPLIT) {
                        mma16816(acc[mt][nt], ah[mt], bl[nt]);
                        mma16816(acc[mt][nt], al[mt], bh[nt]);
                    }
                }
        }
        __syncthreads();
    }

    // epilogue
#pragma unroll
    for (int mt = 0; mt < 4; mt++) {
#pragma unroll
        for (int nt = 0; nt < 4; nt++) {
            const int col = bcol + warp_n * 32 + nt * 8 + (lane & 3) * 2;
            const float b0 = bias[col], b1 = bias[col + 1];
#pragma unroll
            for (int half = 0; half < 2; half++) {
                const int row = brow + warp_m * 64 + mt * 16 + (lane >> 2) + half * 8;
                float2 v;
                v.x = acc[mt][nt][half * 2 + 0] + b0;
                v.y = acc[mt][nt][half * 2 + 1] + b1;
                if (LAYOUT == 0) {
                    *(float2*)(C + (size_t)row * DM + col) = v;
                } else {
                    const int bb = row / NTOK;
                    const int nn = row - bb * NTOK;
                    const int hh = col >> 5, dd = col & 31;
                    *(float2*)(C + (((size_t)bb * NH + hh) * NTOK + nn) * HD + dd) = v;
                }
            }
        }
    }
}

// ---------------------------------------------------------------------------
// Attention: CTA per (window b, head h). 128 threads. float4-vectorized.
// ---------------------------------------------------------------------------
__global__ __launch_bounds__(128)
void attn49(const float* __restrict__ q, const float* __restrict__ k,
            const float* __restrict__ v, const float* __restrict__ mask,
            float* __restrict__ out) {
    const int b = blockIdx.x;
    const int h = blockIdx.y;
    const int tid = threadIdx.x;
    const int warp = tid >> 5, lane = tid & 31;

    __shared__ float4 qs[NTOK][9];   // rows padded to 144B
    __shared__ float4 ks[NTOK][9];
    __shared__ float4 vs[NTOK][9];
    __shared__ float sc[NTOK][52];

    const size_t base = (((size_t)b * NH + h) * NTOK) * HD;
    const float4* qp = (const float4*)(q + base);
    const float4* kp = (const float4*)(k + base);
    const float4* vp = (const float4*)(v + base);

    for (int idx = tid; idx < NTOK * 8; idx += 128) {
        const int n = idx >> 3, g = idx & 7;
        qs[n][g] = qp[idx];
        ks[n][g] = kp[idx];
        vs[n][g] = vp[idx];
    }
    __syncthreads();

    const float* mp = mask + (size_t)b * NTOK * NTOK;
    for (int i = warp; i < NTOK; i += 4) {
        float4 qr[8];
#pragma unroll
        for (int m = 0; m < 8; m++) qr[m] = qs[i][m];
        for (int j = lane; j < NTOK; j += 32) {
            float a = 0.f;
#pragma unroll
            for (int m = 0; m < 8; m++) {
                float4 kv = ks[j][m];
                a += qr[m].x * kv.x + qr[m].y * kv.y + qr[m].z * kv.z + qr[m].w * kv.w;
            }
            sc[i][j] = a * SCALE_F + mp[i * NTOK + j];
        }
    }
    __syncthreads();

    for (int r = warp; r < NTOK; r += 4) {
        float e0 = sc[r][lane];
        float e1 = (lane + 32 < NTOK) ? sc[r][lane + 32] : -3.4e38f;
        float m = fmaxf(e0, e1);
#pragma unroll
        for (int off = 16; off > 0; off >>= 1)
            m = fmaxf(m, __shfl_xor_sync(0xFFFFFFFFu, m, off));
        float x0 = __expf(e0 - m);
        float x1 = (lane + 32 < NTOK) ? __expf(e1 - m) : 0.f;
        float s = x0 + x1;
#pragma unroll
        for (int off = 16; off > 0; off >>= 1)
            s += __shfl_xor_sync(0xFFFFFFFFu, s, off);
        const float inv = 1.f / s;
        sc[r][lane] = x0 * inv;
        if (lane + 32 < NTOK) sc[r][lane + 32] = x1 * inv;
    }
    __syncthreads();

    for (int idx = tid; idx < NTOK * 8; idx += 128) {
        const int i = idx >> 3, g = idx & 7;
        float4 a = make_float4(0.f, 0.f, 0.f, 0.f);
#pragma unroll 7
        for (int j = 0; j < NTOK; j++) {
            const float w = sc[i][j];
            const float4 vv = vs[j][g];
            a.x += w * vv.x;
            a.y += w * vv.y;
            a.z += w * vv.z;
            a.w += w * vv.w;
        }
        *(float4*)(out + ((size_t)b * NTOK + i) * DM + h * HD + g * 4) = a;
    }
}

// ---------------------------------------------------------------------------
extern "C" void kernel_launch(void* const* d_in, const int* in_sizes, int n_in,
                              void* d_out, int out_size) {
    const float* x    = (const float*)d_in[0];
    const float* mask = (const float*)d_in[1];
    const float* Wq   = (const float*)d_in[2];
    const float* bq   = (const float*)d_in[3];
    const float* Wk   = (const float*)d_in[4];
    const float* bk   = (const float*)d_in[5];
    const float* Wv   = (const float*)d_in[6];
    const float* bv   = (const float*)d_in[7];
    const float* Wp   = (const float*)d_in[8];
    const float* bp   = (const float*)d_in[9];

    float *qp, *kp, *vp, *ap;
    __nv_bfloat16 *wth, *wtl;
    cudaGetSymbolAddress((void**)&qp, g_q);
    cudaGetSymbolAddress((void**)&kp, g_k);
    cudaGetSymbolAddress((void**)&vp, g_v);
    cudaGetSymbolAddress((void**)&ap, g_attn);
    cudaGetSymbolAddress((void**)&wth, g_wth);
    cudaGetSymbolAddress((void**)&wtl, g_wtl);

    convW<<<(4 * 384 * 384 + 255) / 256, 256>>>(Wq, Wk, Wv, Wp, wth, wtl);

    dim3 ggrid(3, ROWS / 128);
    // Q, K: plain bf16 (softmax kills the quantization error via SCALE=3e-8)
    gemm_hmma<0, 1><<<ggrid, 256>>>(x, wth + 0 * 147456, wtl + 0 * 147456, bq, qp);
    gemm_hmma<0, 1><<<ggrid, 256>>>(x, wth + 1 * 147456, wtl + 1 * 147456, bk, kp);
    // V: 3-term split (propagates linearly to output)
    gemm_hmma<1, 1><<<ggrid, 256>>>(x, wth + 2 * 147456, wtl + 2 * 147456, bv, vp);

    dim3 agrid(NWIN, NH);
    attn49<<<agrid, 128>>>(qp, kp, vp, mask, ap);

    // Projection: 3-term split
    gemm_hmma<1, 0><<<ggrid, 256>>>(ap, wth + 3 * 147456, wtl + 3 * 147456, bp, (float*)d_out);
}

// round 4
// speedup vs baseline: 4.1549x; 1.3563x over previous
#include <cuda_runtime.h>
#include <cuda_bf16.h>
#include <cstdint>
#include <math.h>

#define ROWS 200704   // 4096 * 49
#define DM   384
#define NWIN 4096
#define NH   12
#define NTOK 49
#define HD   32

// SCALE = 32^-5 (faithful to reference code)
#define SCALE_F 2.9802322387695312e-08f

// ---------------------------------------------------------------------------
// Scratch (__device__ globals; no allocation allowed)
// ---------------------------------------------------------------------------
__device__ __nv_bfloat16 g_xh[(size_t)ROWS * DM];
__device__ __nv_bfloat16 g_xl[(size_t)ROWS * DM];
__device__ float         g_qkv[(size_t)3 * ROWS * DM];   // head-split q,k,v
__device__ __nv_bfloat16 g_oh[(size_t)ROWS * DM];        // attn out hi
__device__ __nv_bfloat16 g_ol[(size_t)ROWS * DM];        // attn out lo
__device__ __nv_bfloat16 g_wth[4 * 384 * 384];           // W^T hi [m][n][k]
__device__ __nv_bfloat16 g_wtl[4 * 384 * 384];           // W^T lo
__device__ float         g_bqkv[3 * 384];                // concat bq,bk,bv

// ---------------------------------------------------------------------------
__device__ __forceinline__ uint32_t smem_u32(const void* p) {
    uint32_t a;
    asm("{ .reg .u64 t; cvta.to.shared.u64 t, %1; cvt.u32.u64 %0, t; }" : "=r"(a) : "l"(p));
    return a;
}
__device__ __forceinline__ void ldsm4(uint32_t& r0, uint32_t& r1, uint32_t& r2, uint32_t& r3,
                                      uint32_t addr) {
    asm volatile("ldmatrix.sync.aligned.m8n8.x4.shared.b16 {%0,%1,%2,%3}, [%4];"
                 : "=r"(r0), "=r"(r1), "=r"(r2), "=r"(r3) : "r"(addr));
}
__device__ __forceinline__ void mma16816(float* d, const uint32_t* a, const uint32_t* b) {
    asm volatile("mma.sync.aligned.m16n8k16.row.col.f32.bf16.bf16.f32 "
                 "{%0,%1,%2,%3}, {%4,%5,%6,%7}, {%8,%9}, {%0,%1,%2,%3};"
                 : "+f"(d[0]), "+f"(d[1]), "+f"(d[2]), "+f"(d[3])
                 : "r"(a[0]), "r"(a[1]), "r"(a[2]), "r"(a[3]), "r"(b[0]), "r"(b[1]));
}
__device__ __forceinline__ void cpa16(uint32_t dst, const void* src) {
    asm volatile("cp.async.cg.shared.global [%0], [%1], 16;" :: "r"(dst), "l"(src));
}
#define CP_COMMIT() asm volatile("cp.async.commit_group;" ::: "memory")

__device__ __forceinline__ uint32_t pack2(float a, float b) {
    __nv_bfloat16 x = __float2bfloat16(a);
    __nv_bfloat16 y = __float2bfloat16(b);
    return (uint32_t)__bfloat16_as_ushort(x) | ((uint32_t)__bfloat16_as_ushort(y) << 16);
}
__device__ __forceinline__ void split_pack(float a, float b, uint32_t& hi, uint32_t& lo) {
    __nv_bfloat16 ah = __float2bfloat16(a);
    __nv_bfloat16 bh = __float2bfloat16(b);
    hi = (uint32_t)__bfloat16_as_ushort(ah) | ((uint32_t)__bfloat16_as_ushort(bh) << 16);
    lo = pack2(a - __bfloat162float(ah), b - __bfloat162float(bh));
}

// ---------------------------------------------------------------------------
// Weight transpose + bf16 hi/lo split; also concat qkv bias.
// ---------------------------------------------------------------------------
__global__ void convW(const float* __restrict__ Wq, const float* __restrict__ Wk,
                      const float* __restrict__ Wv, const float* __restrict__ Wp,
                      const float* __restrict__ bq, const float* __restrict__ bk,
                      const float* __restrict__ bv,
                      __nv_bfloat16* __restrict__ th, __nv_bfloat16* __restrict__ tl,
                      float* __restrict__ bqkv) {
    int idx = blockIdx.x * 256 + threadIdx.x;
    if (idx < 3 * 384)
        bqkv[idx] = (idx < 384) ? bq[idx] : (idx < 768) ? bk[idx - 384] : bv[idx - 768];
    if (idx >= 4 * 384 * 384) return;
    int m = idx / (384 * 384);
    int rem = idx - m * 384 * 384;
    int n = rem / 384, k = rem - (rem / 384) * 384;
    const float* W = (m == 0) ? Wq : (m == 1) ? Wk : (m == 2) ? Wv : Wp;
    float a = W[k * 384 + n];
    __nv_bfloat16 h = __float2bfloat16(a);
    th[idx] = h;
    tl[idx] = __float2bfloat16(a - __bfloat162float(h));
}

// ---------------------------------------------------------------------------
// x fp32 -> bf16 hi/lo
// ---------------------------------------------------------------------------
__global__ void convX(const float* __restrict__ x,
                      __nv_bfloat16* __restrict__ xh, __nv_bfloat16* __restrict__ xl) {
    size_t i = ((size_t)blockIdx.x * 256 + threadIdx.x) * 4;
    if (i >= (size_t)ROWS * DM) return;
    float4 v = *(const float4*)(x + i);
    uint32_t h0, l0, h1, l1;
    split_pack(v.x, v.y, h0, l0);
    split_pack(v.z, v.w, h1, l1);
    *(uint2*)(xh + i) = make_uint2(h0, h1);
    *(uint2*)(xl + i) = make_uint2(l0, l1);
}

// ---------------------------------------------------------------------------
// HMMA GEMM with cp.async 2-stage pipeline.
// MODE 1: proj  (all CTAs split, row-major out, B rows [0,384))
// MODE 2: qkv   (split iff bcol>=768, head-split out into g_qkv, B rows [0,1152))
// CTA 128x128, BK=32, 256 threads (8 warps 2x4), warp tile 64x32.
// smem: 2 stages x 4 tiles (Ah,Bh,Al,Bl) x 128 rows x 80B = 80KB.
// ---------------------------------------------------------------------------
#define RB     80        // bytes per smem row (32 bf16 + 16B pad)
#define TILE_B 10240     // 128 * RB
#define STG_B  40960     // 4 tiles
#define T_AH   0
#define T_BH   10240
#define T_AL   20480
#define T_BL   30720
#define SMEM_GEMM 81920

template <int MODE>
__global__ __launch_bounds__(256, 2)
void gemm_cp(const __nv_bfloat16* __restrict__ Ah, const __nv_bfloat16* __restrict__ Al,
             const __nv_bfloat16* __restrict__ Bh, const __nv_bfloat16* __restrict__ Bl,
             const float* __restrict__ bias, float* __restrict__ Cbase) {
    extern __shared__ char smem[];
    const uint32_t sb = smem_u32(smem);
    const int tid = threadIdx.x;
    const int wid = tid >> 5, lane = tid & 31;
    const int warp_m = wid & 1, warp_n = wid >> 1;
    const int brow = blockIdx.y * 128;
    const int bcol = blockIdx.x * 128;
    const bool split = (MODE == 1) || (bcol >= 768);

    float acc[4][4][4];
#pragma unroll
    for (int i = 0; i < 4; i++)
#pragma unroll
        for (int j = 0; j < 4; j++)
#pragma unroll
            for (int c = 0; c < 4; c++) acc[i][j][c] = 0.f;

    // cp.async assignment: per tile, thread handles chunks tid and tid+256
    const int r0 = tid >> 2, q0 = tid & 3;            // chunk tid
    const int r1 = (tid + 256) >> 2, q1 = tid & 3;    // chunk tid+256
    const size_t aoff0 = (size_t)(brow + r0) * DM + q0 * 8;
    const size_t aoff1 = (size_t)(brow + r1) * DM + q1 * 8;
    const size_t boff0 = (size_t)(bcol + r0) * DM + q0 * 8;
    const size_t boff1 = (size_t)(bcol + r1) * DM + q1 * 8;
    const uint32_t d0 = r0 * RB + q0 * 16;
    const uint32_t d1 = r1 * RB + q1 * 16;

    auto issue = [&](int kc, int s) {
        const uint32_t base = sb + s * STG_B;
        const int ko = kc * 32;
        cpa16(base + T_AH + d0, Ah + aoff0 + ko);
        cpa16(base + T_AH + d1, Ah + aoff1 + ko);
        cpa16(base + T_BH + d0, Bh + boff0 + ko);
        cpa16(base + T_BH + d1, Bh + boff1 + ko);
        if (split) {
            cpa16(base + T_AL + d0, Al + aoff0 + ko);
            cpa16(base + T_AL + d1, Al + aoff1 + ko);
            cpa16(base + T_BL + d0, Bl + boff0 + ko);
            cpa16(base + T_BL + d1, Bl + boff1 + ko);
        }
        CP_COMMIT();
    };

    const uint32_t a_off = (warp_m * 64 + (lane & 7) + ((lane >> 3) & 1) * 8) * RB
                         + ((lane >> 4) & 1) * 16;
    const uint32_t b_off = (warp_n * 32 + (lane & 7) + ((lane >> 4) & 1) * 8) * RB
                         + ((lane >> 3) & 1) * 16;

    issue(0, 0);

    for (int kc = 0; kc < 12; kc++) {
        if (kc < 11) {
            issue(kc + 1, (kc + 1) & 1);
            asm volatile("cp.async.wait_group 1;" ::: "memory");
        } else {
            asm volatile("cp.async.wait_group 0;" ::: "memory");
        }
        __syncthreads();

        const uint32_t base = sb + (kc & 1) * STG_B;
#pragma unroll
        for (int st = 0; st < 2; st++) {
            const uint32_t so = st * 32;
            uint32_t a[4][4], b[4][2];
#pragma unroll
            for (int mt = 0; mt < 4; mt++)
                ldsm4(a[mt][0], a[mt][1], a[mt][2], a[mt][3],
                      base + T_AH + a_off + mt * 16 * RB + so);
#pragma unroll
            for (int p = 0; p < 2; p++)
                ldsm4(b[2 * p][0], b[2 * p][1], b[2 * p + 1][0], b[2 * p + 1][1],
                      base + T_BH + b_off + p * 16 * RB + so);
#pragma unroll
            for (int mt = 0; mt < 4; mt++)
#pragma unroll
                for (int nt = 0; nt < 4; nt++)
                    mma16816(acc[mt][nt], a[mt], b[nt]);

            if (split) {
                // hl: Ah * Bl
#pragma unroll
                for (int p = 0; p < 2; p++)
                    ldsm4(b[2 * p][0], b[2 * p][1], b[2 * p + 1][0], b[2 * p + 1][1],
                          base + T_BL + b_off + p * 16 * RB + so);
#pragma unroll
                for (int mt = 0; mt < 4; mt++)
#pragma unroll
                    for (int nt = 0; nt < 4; nt++)
                        mma16816(acc[mt][nt], a[mt], b[nt]);
                // lh: Al * Bh
#pragma unroll
                for (int mt = 0; mt < 4; mt++)
                    ldsm4(a[mt][0], a[mt][1], a[mt][2], a[mt][3],
                          base + T_AL + a_off + mt * 16 * RB + so);
#pragma unroll
                for (int p = 0; p < 2; p++)
                    ldsm4(b[2 * p][0], b[2 * p][1], b[2 * p + 1][0], b[2 * p + 1][1],
                          base + T_BH + b_off + p * 16 * RB + so);
#pragma unroll
                for (int mt = 0; mt < 4; mt++)
#pragma unroll
                    for (int nt = 0; nt < 4; nt++)
                        mma16816(acc[mt][nt], a[mt], b[nt]);
            }
        }
        __syncthreads();
    }

    // epilogue
#pragma unroll
    for (int mt = 0; mt < 4; mt++) {
#pragma unroll
        for (int nt = 0; nt < 4; nt++) {
            const int gcol = bcol + warp_n * 32 + nt * 8 + (lane & 3) * 2;
            const float b0 = bias[gcol], b1 = bias[gcol + 1];
#pragma unroll
            for (int half = 0; half < 2; half++) {
                const int row = brow + warp_m * 64 + mt * 16 + (lane >> 2) + half * 8;
                float2 v;
                v.x = acc[mt][nt][half * 2 + 0] + b0;
                v.y = acc[mt][nt][half * 2 + 1] + b1;
                if (MODE == 1) {
                    *(float2*)(Cbase + (size_t)row * DM + gcol) = v;
                } else {
                    const int m = gcol / 384;
                    const int cm = gcol - m * 384;
                    const int hh = cm >> 5, dd = cm & 31;
                    const int bb = row / NTOK;
                    const int nn = row - bb * NTOK;
                    *(float2*)(Cbase + (size_t)m * ROWS * DM +
                               (((size_t)bb * NH + hh) * NTOK + nn) * HD + dd) = v;
                }
            }
        }
    }
}

// ---------------------------------------------------------------------------
// Attention: CTA per (head h = blockIdx.x, window b = blockIdx.y).
// Output written as bf16 hi/lo row-major for the projection GEMM.
// ---------------------------------------------------------------------------
__global__ __launch_bounds__(128)
void attn49(const float* __restrict__ q, const float* __restrict__ k,
            const float* __restrict__ v, const float* __restrict__ mask,
            __nv_bfloat16* __restrict__ oh, __nv_bfloat16* __restrict__ ol) {
    const int h = blockIdx.x;
    const int b = blockIdx.y;
    const int tid = threadIdx.x;
    const int warp = tid >> 5, lane = tid & 31;

    __shared__ float4 qs[NTOK][9];
    __shared__ float4 ks[NTOK][9];
    __shared__ float4 vs[NTOK][9];
    __shared__ float sc[NTOK][52];

    const size_t base = (((size_t)b * NH + h) * NTOK) * HD;
    const float4* qp = (const float4*)(q + base);
    const float4* kp = (const float4*)(k + base);
    const float4* vp = (const float4*)(v + base);

    for (int idx = tid; idx < NTOK * 8; idx += 128) {
        const int n = idx >> 3, g = idx & 7;
        qs[n][g] = qp[idx];
        ks[n][g] = kp[idx];
        vs[n][g] = vp[idx];
    }
    __syncthreads();

    const float* mp = mask + (size_t)b * NTOK * NTOK;
    for (int i = warp; i < NTOK; i += 4) {
        float4 qr[8];
#pragma unroll
        for (int m = 0; m < 8; m++) qr[m] = qs[i][m];
        for (int j = lane; j < NTOK; j += 32) {
            float a = 0.f;
#pragma unroll
            for (int m = 0; m < 8; m++) {
                float4 kv = ks[j][m];
                a += qr[m].x * kv.x + qr[m].y * kv.y + qr[m].z * kv.z + qr[m].w * kv.w;
            }
            sc[i][j] = a * SCALE_F + mp[i * NTOK + j];
        }
    }
    __syncthreads();

    for (int r = warp; r < NTOK; r += 4) {
        float e0 = sc[r][lane];
        float e1 = (lane + 32 < NTOK) ? sc[r][lane + 32] : -3.4e38f;
        float m = fmaxf(e0, e1);
#pragma unroll
        for (int off = 16; off > 0; off >>= 1)
            m = fmaxf(m, __shfl_xor_sync(0xFFFFFFFFu, m, off));
        float x0 = __expf(e0 - m);
        float x1 = (lane + 32 < NTOK) ? __expf(e1 - m) : 0.f;
        float s = x0 + x1;
#pragma unroll
        for (int off = 16; off > 0; off >>= 1)
            s += __shfl_xor_sync(0xFFFFFFFFu, s, off);
        const float inv = 1.f / s;
        sc[r][lane] = x0 * inv;
        if (lane + 32 < NTOK) sc[r][lane + 32] = x1 * inv;
    }
    __syncthreads();

    for (int idx = tid; idx < NTOK * 8; idx += 128) {
        const int i = idx >> 3, g = idx & 7;
        float4 a = make_float4(0.f, 0.f, 0.f, 0.f);
#pragma unroll 7
        for (int j = 0; j < NTOK; j++) {
            const float w = sc[i][j];
            const float4 vv = vs[j][g];
            a.x += w * vv.x;
            a.y += w * vv.y;
            a.z += w * vv.z;
            a.w += w * vv.w;
        }
        uint32_t h0, l0, h1, l1;
        split_pack(a.x, a.y, h0, l0);
        split_pack(a.z, a.w, h1, l1);
        const size_t off = ((size_t)b * NTOK + i) * DM + h * HD + g * 4;
        *(uint2*)(oh + off) = make_uint2(h0, h1);
        *(uint2*)(ol + off) = make_uint2(l0, l1);
    }
}

// ---------------------------------------------------------------------------
extern "C" void kernel_launch(void* const* d_in, const int* in_sizes, int n_in,
                              void* d_out, int out_size) {
    const float* x    = (const float*)d_in[0];
    const float* mask = (const float*)d_in[1];
    const float* Wq   = (const float*)d_in[2];
    const float* bq   = (const float*)d_in[3];
    const float* Wk   = (const float*)d_in[4];
    const float* bk   = (const float*)d_in[5];
    const float* Wv   = (const float*)d_in[6];
    const float* bv   = (const float*)d_in[7];
    const float* Wp   = (const float*)d_in[8];
    const float* bp   = (const float*)d_in[9];

    __nv_bfloat16 *xh, *xl, *oh, *ol, *wth, *wtl;
    float *qkv, *bqkv;
    cudaGetSymbolAddress((void**)&xh, g_xh);
    cudaGetSymbolAddress((void**)&xl, g_xl);
    cudaGetSymbolAddress((void**)&oh, g_oh);
    cudaGetSymbolAddress((void**)&ol, g_ol);
    cudaGetSymbolAddress((void**)&wth, g_wth);
    cudaGetSymbolAddress((void**)&wtl, g_wtl);
    cudaGetSymbolAddress((void**)&qkv, g_qkv);
    cudaGetSymbolAddress((void**)&bqkv, g_bqkv);

    cudaFuncSetAttribute(gemm_cp<1>, cudaFuncAttributeMaxDynamicSharedMemorySize, SMEM_GEMM);
    cudaFuncSetAttribute(gemm_cp<2>, cudaFuncAttributeMaxDynamicSharedMemorySize, SMEM_GEMM);

    convW<<<(4 * 384 * 384 + 255) / 256, 256>>>(Wq, Wk, Wv, Wp, bq, bk, bv, wth, wtl, bqkv);
    convX<<<(int)(((size_t)ROWS * DM / 4 + 255) / 256), 256>>>(x, xh, xl);

    // fused QKV: B rows 0..1151 over concatenated W^T (m=0,1,2 contiguous)
    dim3 qkvgrid(9, ROWS / 128);
    gemm_cp<2><<<qkvgrid, 256, SMEM_GEMM>>>(xh, xl, wth, wtl, bqkv, qkv);

    dim3 agrid(NH, NWIN);
    attn49<<<agrid, 128>>>(qkv, qkv + (size_t)ROWS * DM, qkv + (size_t)2 * ROWS * DM,
                           mask, oh, ol);

    dim3 pgrid(3, ROWS / 128);
    gemm_cp<1><<<pgrid, 256, SMEM_GEMM>>>(oh, ol, wth + 3 * 147456, wtl + 3 * 147456,
                                          bp, (float*)d_out);
}

// round 5
// speedup vs baseline: 4.6284x; 1.1140x over previous
#include <cuda_runtime.h>
#include <cuda_bf16.h>
#include <cstdint>
#include <math.h>

#define ROWS 200704   // 4096 * 49
#define DM   384
#define NWIN 4096
#define NH   12
#define NTOK 49
#define HD   32

// SCALE = 32^-5 (faithful to reference code)
#define SCALE_F 2.9802322387695312e-08f

// ---------------------------------------------------------------------------
// Scratch (__device__ globals; no allocation allowed)
// ---------------------------------------------------------------------------
__device__ __nv_bfloat16 g_xh[(size_t)ROWS * DM];
__device__ __nv_bfloat16 g_xl[(size_t)ROWS * DM];
__device__ float         g_qkv[(size_t)3 * ROWS * DM];   // head-split q,k,v
__device__ __nv_bfloat16 g_oh[(size_t)ROWS * DM];        // attn out hi
__device__ __nv_bfloat16 g_ol[(size_t)ROWS * DM];        // attn out lo
__device__ __nv_bfloat16 g_wth[4 * 384 * 384];           // W^T hi [m][n][k]
__device__ __nv_bfloat16 g_wtl[4 * 384 * 384];           // W^T lo
__device__ float         g_bqkv[3 * 384];                // concat bq,bk,bv

// ---------------------------------------------------------------------------
__device__ __forceinline__ uint32_t smem_u32(const void* p) {
    uint32_t a;
    asm("{ .reg .u64 t; cvta.to.shared.u64 t, %1; cvt.u32.u64 %0, t; }" : "=r"(a) : "l"(p));
    return a;
}
__device__ __forceinline__ void ldsm4(uint32_t& r0, uint32_t& r1, uint32_t& r2, uint32_t& r3,
                                      uint32_t addr) {
    asm volatile("ldmatrix.sync.aligned.m8n8.x4.shared.b16 {%0,%1,%2,%3}, [%4];"
                 : "=r"(r0), "=r"(r1), "=r"(r2), "=r"(r3) : "r"(addr));
}
__device__ __forceinline__ void mma16816(float* d, const uint32_t* a, const uint32_t* b) {
    asm volatile("mma.sync.aligned.m16n8k16.row.col.f32.bf16.bf16.f32 "
                 "{%0,%1,%2,%3}, {%4,%5,%6,%7}, {%8,%9}, {%0,%1,%2,%3};"
                 : "+f"(d[0]), "+f"(d[1]), "+f"(d[2]), "+f"(d[3])
                 : "r"(a[0]), "r"(a[1]), "r"(a[2]), "r"(a[3]), "r"(b[0]), "r"(b[1]));
}
__device__ __forceinline__ void cpa16(uint32_t dst, const void* src) {
    asm volatile("cp.async.cg.shared.global [%0], [%1], 16;" :: "r"(dst), "l"(src));
}
#define CP_COMMIT() asm volatile("cp.async.commit_group;" ::: "memory")

__device__ __forceinline__ uint32_t pack2(float a, float b) {
    __nv_bfloat16 x = __float2bfloat16(a);
    __nv_bfloat16 y = __float2bfloat16(b);
    return (uint32_t)__bfloat16_as_ushort(x) | ((uint32_t)__bfloat16_as_ushort(y) << 16);
}
__device__ __forceinline__ void split_pack(float a, float b, uint32_t& hi, uint32_t& lo) {
    __nv_bfloat16 ah = __float2bfloat16(a);
    __nv_bfloat16 bh = __float2bfloat16(b);
    hi = (uint32_t)__bfloat16_as_ushort(ah) | ((uint32_t)__bfloat16_as_ushort(bh) << 16);
    lo = pack2(a - __bfloat162float(ah), b - __bfloat162float(bh));
}

// ---------------------------------------------------------------------------
// Weight transpose + bf16 hi/lo split; also concat qkv bias.
// ---------------------------------------------------------------------------
__global__ void convW(const float* __restrict__ Wq, const float* __restrict__ Wk,
                      const float* __restrict__ Wv, const float* __restrict__ Wp,
                      const float* __restrict__ bq, const float* __restrict__ bk,
                      const float* __restrict__ bv,
                      __nv_bfloat16* __restrict__ th, __nv_bfloat16* __restrict__ tl,
                      float* __restrict__ bqkv) {
    int idx = blockIdx.x * 256 + threadIdx.x;
    if (idx < 3 * 384)
        bqkv[idx] = (idx < 384) ? bq[idx] : (idx < 768) ? bk[idx - 384] : bv[idx - 768];
    if (idx >= 4 * 384 * 384) return;
    int m = idx / (384 * 384);
    int rem = idx - m * 384 * 384;
    int n = rem / 384, k = rem - (rem / 384) * 384;
    const float* W = (m == 0) ? Wq : (m == 1) ? Wk : (m == 2) ? Wv : Wp;
    float a = W[k * 384 + n];
    __nv_bfloat16 h = __float2bfloat16(a);
    th[idx] = h;
    tl[idx] = __float2bfloat16(a - __bfloat162float(h));
}

// ---------------------------------------------------------------------------
// x fp32 -> bf16 hi/lo
// ---------------------------------------------------------------------------
__global__ void convX(const float* __restrict__ x,
                      __nv_bfloat16* __restrict__ xh, __nv_bfloat16* __restrict__ xl) {
    size_t i = ((size_t)blockIdx.x * 256 + threadIdx.x) * 4;
    if (i >= (size_t)ROWS * DM) return;
    float4 v = *(const float4*)(x + i);
    uint32_t h0, l0, h1, l1;
    split_pack(v.x, v.y, h0, l0);
    split_pack(v.z, v.w, h1, l1);
    *(uint2*)(xh + i) = make_uint2(h0, h1);
    *(uint2*)(xl + i) = make_uint2(l0, l1);
}

// ---------------------------------------------------------------------------
// HMMA GEMM with cp.async 2-stage pipeline.
// MODE 1: proj  (all CTAs split, row-major out, B rows [0,384))
// MODE 2: qkv   (split iff bcol>=768, head-split out into g_qkv, B rows [0,1152))
// ---------------------------------------------------------------------------
#define RB     80        // bytes per smem row (32 bf16 + 16B pad)
#define TILE_B 10240     // 128 * RB
#define STG_B  40960     // 4 tiles
#define T_AH   0
#define T_BH   10240
#define T_AL   20480
#define T_BL   30720
#define SMEM_GEMM 81920

template <int MODE>
__global__ __launch_bounds__(256, 2)
void gemm_cp(const __nv_bfloat16* __restrict__ Ah, const __nv_bfloat16* __restrict__ Al,
             const __nv_bfloat16* __restrict__ Bh, const __nv_bfloat16* __restrict__ Bl,
             const float* __restrict__ bias, float* __restrict__ Cbase) {
    extern __shared__ char smem[];
    const uint32_t sb = smem_u32(smem);
    const int tid = threadIdx.x;
    const int wid = tid >> 5, lane = tid & 31;
    const int warp_m = wid & 1, warp_n = wid >> 1;
    const int brow = blockIdx.y * 128;
    const int bcol = blockIdx.x * 128;
    const bool split = (MODE == 1) || (bcol >= 768);

    float acc[4][4][4];
#pragma unroll
    for (int i = 0; i < 4; i++)
#pragma unroll
        for (int j = 0; j < 4; j++)
#pragma unroll
            for (int c = 0; c < 4; c++) acc[i][j][c] = 0.f;

    const int r0 = tid >> 2, q0 = tid & 3;
    const int r1 = (tid + 256) >> 2, q1 = tid & 3;
    const size_t aoff0 = (size_t)(brow + r0) * DM + q0 * 8;
    const size_t aoff1 = (size_t)(brow + r1) * DM + q1 * 8;
    const size_t boff0 = (size_t)(bcol + r0) * DM + q0 * 8;
    const size_t boff1 = (size_t)(bcol + r1) * DM + q1 * 8;
    const uint32_t d0 = r0 * RB + q0 * 16;
    const uint32_t d1 = r1 * RB + q1 * 16;

    auto issue = [&](int kc, int s) {
        const uint32_t base = sb + s * STG_B;
        const int ko = kc * 32;
        cpa16(base + T_AH + d0, Ah + aoff0 + ko);
        cpa16(base + T_AH + d1, Ah + aoff1 + ko);
        cpa16(base + T_BH + d0, Bh + boff0 + ko);
        cpa16(base + T_BH + d1, Bh + boff1 + ko);
        if (split) {
            cpa16(base + T_AL + d0, Al + aoff0 + ko);
            cpa16(base + T_AL + d1, Al + aoff1 + ko);
            cpa16(base + T_BL + d0, Bl + boff0 + ko);
            cpa16(base + T_BL + d1, Bl + boff1 + ko);
        }
        CP_COMMIT();
    };

    const uint32_t a_off = (warp_m * 64 + (lane & 7) + ((lane >> 3) & 1) * 8) * RB
                         + ((lane >> 4) & 1) * 16;
    const uint32_t b_off = (warp_n * 32 + (lane & 7) + ((lane >> 4) & 1) * 8) * RB
                         + ((lane >> 3) & 1) * 16;

    issue(0, 0);

    for (int kc = 0; kc < 12; kc++) {
        if (kc < 11) {
            issue(kc + 1, (kc + 1) & 1);
            asm volatile("cp.async.wait_group 1;" ::: "memory");
        } else {
            asm volatile("cp.async.wait_group 0;" ::: "memory");
        }
        __syncthreads();

        const uint32_t base = sb + (kc & 1) * STG_B;
#pragma unroll
        for (int st = 0; st < 2; st++) {
            const uint32_t so = st * 32;
            uint32_t a[4][4], bh[4][2], bl[4][2];
#pragma unroll
            for (int mt = 0; mt < 4; mt++)
                ldsm4(a[mt][0], a[mt][1], a[mt][2], a[mt][3],
                      base + T_AH + a_off + mt * 16 * RB + so);
#pragma unroll
            for (int p = 0; p < 2; p++)
                ldsm4(bh[2 * p][0], bh[2 * p][1], bh[2 * p + 1][0], bh[2 * p + 1][1],
                      base + T_BH + b_off + p * 16 * RB + so);
#pragma unroll
            for (int mt = 0; mt < 4; mt++)
#pragma unroll
                for (int nt = 0; nt < 4; nt++)
                    mma16816(acc[mt][nt], a[mt], bh[nt]);

            if (split) {
                // hl: Ah * Bl (reuse a)
#pragma unroll
                for (int p = 0; p < 2; p++)
                    ldsm4(bl[2 * p][0], bl[2 * p][1], bl[2 * p + 1][0], bl[2 * p + 1][1],
                          base + T_BL + b_off + p * 16 * RB + so);
#pragma unroll
                for (int mt = 0; mt < 4; mt++)
#pragma unroll
                    for (int nt = 0; nt < 4; nt++)
                        mma16816(acc[mt][nt], a[mt], bl[nt]);
                // lh: Al * Bh (reuse bh regs)
#pragma unroll
                for (int mt = 0; mt < 4; mt++)
                    ldsm4(a[mt][0], a[mt][1], a[mt][2], a[mt][3],
                          base + T_AL + a_off + mt * 16 * RB + so);
#pragma unroll
                for (int mt = 0; mt < 4; mt++)
#pragma unroll
                    for (int nt = 0; nt < 4; nt++)
                        mma16816(acc[mt][nt], a[mt], bh[nt]);
            }
        }
        __syncthreads();
    }

    // epilogue
#pragma unroll
    for (int mt = 0; mt < 4; mt++) {
#pragma unroll
        for (int nt = 0; nt < 4; nt++) {
            const int gcol = bcol + warp_n * 32 + nt * 8 + (lane & 3) * 2;
            const float b0 = bias[gcol], b1 = bias[gcol + 1];
#pragma unroll
            for (int half = 0; half < 2; half++) {
                const int row = brow + warp_m * 64 + mt * 16 + (lane >> 2) + half * 8;
                float2 v;
                v.x = acc[mt][nt][half * 2 + 0] + b0;
                v.y = acc[mt][nt][half * 2 + 1] + b1;
                if (MODE == 1) {
                    *(float2*)(Cbase + (size_t)row * DM + gcol) = v;
                } else {
                    const int m = gcol / 384;
                    const int cm = gcol - m * 384;
                    const int hh = cm >> 5, dd = cm & 31;
                    const int bb = row / NTOK;
                    const int nn = row - bb * NTOK;
                    *(float2*)(Cbase + (size_t)m * ROWS * DM +
                               (((size_t)bb * NH + hh) * NTOK + nn) * HD + dd) = v;
                }
            }
        }
    }
}

// ---------------------------------------------------------------------------
// Attention: CTA per (head h = blockIdx.x, window b = blockIdx.y), 128 thr.
// K and V are read from smem ONCE (register-cached); q broadcast per row.
// smem row stride 36 floats -> quarter-warp conflict-free.
// ---------------------------------------------------------------------------
__global__ __launch_bounds__(128)
void attn49(const float* __restrict__ q, const float* __restrict__ k,
            const float* __restrict__ v, const float* __restrict__ mask,
            __nv_bfloat16* __restrict__ oh, __nv_bfloat16* __restrict__ ol) {
    const int h = blockIdx.x;
    const int b = blockIdx.y;
    const int tid = threadIdx.x;
    const int warp = tid >> 5, lane = tid & 31;

    __shared__ float qs[NTOK][36];
    __shared__ float ks[NTOK][36];
    __shared__ float vs[NTOK][36];
    __shared__ float sc[64][52];     // padded rows so i<64 reads are in-bounds

    const size_t base = (((size_t)b * NH + h) * NTOK) * HD;
    const float4* qp = (const float4*)(q + base);
    const float4* kp = (const float4*)(k + base);
    const float4* vp = (const float4*)(v + base);

    for (int idx = tid; idx < NTOK * 8; idx += 128) {
        const int n = idx >> 3, g = idx & 7;
        *(float4*)&qs[n][g * 4] = qp[idx];
        *(float4*)&ks[n][g * 4] = kp[idx];
        *(float4*)&vs[n][g * 4] = vp[idx];
    }
    // zero pad rows of sc (rows 49..63) so AV reads are defined
    for (int idx = tid; idx < 15 * 52; idx += 128)
        sc[49 + idx / 52][idx % 52] = 0.f;
    __syncthreads();

    // ---- scores: group p (64 threads) covers i-range; thread owns column j.
    {
        const int p = tid >> 6;          // 0 or 1
        const int j = tid & 63;
        const float* mp = mask + (size_t)b * NTOK * NTOK;
        if (j < NTOK) {
            float4 kr[8];
#pragma unroll
            for (int m = 0; m < 8; m++) kr[m] = *(const float4*)&ks[j][m * 4];
            const int i0 = p ? 25 : 0;
            const int i1 = p ? NTOK : 25;
            for (int i = i0; i < i1; i++) {
                float a = 0.f;
#pragma unroll
                for (int m = 0; m < 8; m++) {
                    const float4 qv = *(const float4*)&qs[i][m * 4];  // broadcast
                    a += qv.x * kr[m].x + qv.y * kr[m].y + qv.z * kr[m].z + qv.w * kr[m].w;
                }
                sc[i][j] = a * SCALE_F + mp[i * NTOK + j];
            }
        }
    }
    __syncthreads();

    // ---- softmax: warp per row
    for (int r = warp; r < NTOK; r += 4) {
        float e0 = sc[r][lane];
        float e1 = (lane + 32 < NTOK) ? sc[r][lane + 32] : -3.4e38f;
        float m = fmaxf(e0, e1);
#pragma unroll
        for (int off = 16; off > 0; off >>= 1)
            m = fmaxf(m, __shfl_xor_sync(0xFFFFFFFFu, m, off));
        float x0 = __expf(e0 - m);
        float x1 = (lane + 32 < NTOK) ? __expf(e1 - m) : 0.f;
        float s = x0 + x1;
#pragma unroll
        for (int off = 16; off > 0; off >>= 1)
            s += __shfl_xor_sync(0xFFFFFFFFu, s, off);
        const float inv = 1.f / s;
        sc[r][lane] = x0 * inv;
        if (lane + 32 < NTOK) sc[r][lane + 32] = x1 * inv;
    }
    __syncthreads();

    // ---- AV: thread owns d-group g and rows i = iset + 16r (r=0..3)
    {
        const int g = tid & 7;
        const int iset = tid >> 3;       // 0..15
        float4 a0 = make_float4(0.f, 0.f, 0.f, 0.f);
        float4 a1 = a0, a2 = a0, a3 = a0;
        for (int j = 0; j < NTOK; j++) {
            const float4 vv = *(const float4*)&vs[j][g * 4];   // 8 distinct, dedup'd
            const float w0 = sc[iset][j];
            const float w1 = sc[iset + 16][j];
            const float w2 = sc[iset + 32][j];
            const float w3 = sc[iset + 48][j];                 // pad rows are zero
            a0.x += w0 * vv.x; a0.y += w0 * vv.y; a0.z += w0 * vv.z; a0.w += w0 * vv.w;
            a1.x += w1 * vv.x; a1.y += w1 * vv.y; a1.z += w1 * vv.z; a1.w += w1 * vv.w;
            a2.x += w2 * vv.x; a2.y += w2 * vv.y; a2.z += w2 * vv.z; a2.w += w2 * vv.w;
            a3.x += w3 * vv.x; a3.y += w3 * vv.y; a3.z += w3 * vv.z; a3.w += w3 * vv.w;
        }
        float4 accs[4] = {a0, a1, a2, a3};
#pragma unroll
        for (int r = 0; r < 4; r++) {
            const int i = iset + 16 * r;
            if (i < NTOK) {
                uint32_t h0, l0, h1, l1;
                split_pack(accs[r].x, accs[r].y, h0, l0);
                split_pack(accs[r].z, accs[r].w, h1, l1);
                const size_t off = ((size_t)b * NTOK + i) * DM + h * HD + g * 4;
                *(uint2*)(oh + off) = make_uint2(h0, h1);
                *(uint2*)(ol + off) = make_uint2(l0, l1);
            }
        }
    }
}

// ---------------------------------------------------------------------------
extern "C" void kernel_launch(void* const* d_in, const int* in_sizes, int n_in,
                              void* d_out, int out_size) {
    const float* x    = (const float*)d_in[0];
    const float* mask = (const float*)d_in[1];
    const float* Wq   = (const float*)d_in[2];
    const float* bq   = (const float*)d_in[3];
    const float* Wk   = (const float*)d_in[4];
    const float* bk   = (const float*)d_in[5];
    const float* Wv   = (const float*)d_in[6];
    const float* bv   = (const float*)d_in[7];
    const float* Wp   = (const float*)d_in[8];
    const float* bp   = (const float*)d_in[9];

    __nv_bfloat16 *xh, *xl, *oh, *ol, *wth, *wtl;
    float *qkv, *bqkv;
    cudaGetSymbolAddress((void**)&xh, g_xh);
    cudaGetSymbolAddress((void**)&xl, g_xl);
    cudaGetSymbolAddress((void**)&oh, g_oh);
    cudaGetSymbolAddress((void**)&ol, g_ol);
    cudaGetSymbolAddress((void**)&wth, g_wth);
    cudaGetSymbolAddress((void**)&wtl, g_wtl);
    cudaGetSymbolAddress((void**)&qkv, g_qkv);
    cudaGetSymbolAddress((void**)&bqkv, g_bqkv);

    cudaFuncSetAttribute(gemm_cp<1>, cudaFuncAttributeMaxDynamicSharedMemorySize, SMEM_GEMM);
    cudaFuncSetAttribute(gemm_cp<2>, cudaFuncAttributeMaxDynamicSharedMemorySize, SMEM_GEMM);

    convW<<<(4 * 384 * 384 + 255) / 256, 256>>>(Wq, Wk, Wv, Wp, bq, bk, bv, wth, wtl, bqkv);
    convX<<<(int)(((size_t)ROWS * DM / 4 + 255) / 256), 256>>>(x, xh, xl);

    dim3 qkvgrid(9, ROWS / 128);
    gemm_cp<2><<<qkvgrid, 256, SMEM_GEMM>>>(xh, xl, wth, wtl, bqkv, qkv);

    dim3 agrid(NH, NWIN);
    attn49<<<agrid, 128>>>(qkv, qkv + (size_t)ROWS * DM, qkv + (size_t)2 * ROWS * DM,
                           mask, oh, ol);

    dim3 pgrid(3, ROWS / 128);
    gemm_cp<1><<<pgrid, 256, SMEM_GEMM>>>(oh, ol, wth + 3 * 147456, wtl + 3 * 147456,
                                          bp, (float*)d_out);
}

// round 6
// speedup vs baseline: 5.5893x; 1.2076x over previous
#include <cuda_runtime.h>
#include <cuda_bf16.h>
#include <cstdint>
#include <math.h>

#define ROWS 200704   // 4096 * 49
#define DM   384
#define NWIN 4096
#define NH   12
#define NTOK 49
#define HD   32

// SCALE = 32^-5 (faithful to reference code)
#define SCALE_F 2.9802322387695312e-08f

// ---------------------------------------------------------------------------
// Scratch (__device__ globals; no allocation allowed)
// ---------------------------------------------------------------------------
__device__ __nv_bfloat16 g_xh[(size_t)ROWS * DM];
__device__ __nv_bfloat16 g_xl[(size_t)ROWS * DM];
__device__ __nv_bfloat16 g_qk[(size_t)2 * ROWS * DM];    // q,k head-split bf16
__device__ __nv_bfloat16 g_vh[(size_t)ROWS * DM];        // v head-split hi
__device__ __nv_bfloat16 g_vl[(size_t)ROWS * DM];        // v head-split lo
__device__ __nv_bfloat16 g_oh[(size_t)ROWS * DM];        // attn out hi
__device__ __nv_bfloat16 g_ol[(size_t)ROWS * DM];        // attn out lo
__device__ __nv_bfloat16 g_wth[4 * 384 * 384];           // W^T hi [m][n][k]
__device__ __nv_bfloat16 g_wtl[4 * 384 * 384];           // W^T lo
__device__ float         g_bqkv[3 * 384];                // concat bq,bk,bv

// ---------------------------------------------------------------------------
__device__ __forceinline__ uint32_t smem_u32(const void* p) {
    uint32_t a;
    asm("{ .reg .u64 t; cvta.to.shared.u64 t, %1; cvt.u32.u64 %0, t; }" : "=r"(a) : "l"(p));
    return a;
}
__device__ __forceinline__ void ldsm4(uint32_t& r0, uint32_t& r1, uint32_t& r2, uint32_t& r3,
                                      uint32_t addr) {
    asm volatile("ldmatrix.sync.aligned.m8n8.x4.shared.b16 {%0,%1,%2,%3}, [%4];"
                 : "=r"(r0), "=r"(r1), "=r"(r2), "=r"(r3) : "r"(addr));
}
__device__ __forceinline__ void ldsm4t(uint32_t& r0, uint32_t& r1, uint32_t& r2, uint32_t& r3,
                                       uint32_t addr) {
    asm volatile("ldmatrix.sync.aligned.m8n8.x4.trans.shared.b16 {%0,%1,%2,%3}, [%4];"
                 : "=r"(r0), "=r"(r1), "=r"(r2), "=r"(r3) : "r"(addr));
}
__device__ __forceinline__ void mma16816(float* d, const uint32_t* a, const uint32_t* b) {
    asm volatile("mma.sync.aligned.m16n8k16.row.col.f32.bf16.bf16.f32 "
                 "{%0,%1,%2,%3}, {%4,%5,%6,%7}, {%8,%9}, {%0,%1,%2,%3};"
                 : "+f"(d[0]), "+f"(d[1]), "+f"(d[2]), "+f"(d[3])
                 : "r"(a[0]), "r"(a[1]), "r"(a[2]), "r"(a[3]), "r"(b[0]), "r"(b[1]));
}
__device__ __forceinline__ void cpa16(uint32_t dst, const void* src) {
    asm volatile("cp.async.cg.shared.global [%0], [%1], 16;" :: "r"(dst), "l"(src));
}
#define CP_COMMIT() asm volatile("cp.async.commit_group;" ::: "memory")

__device__ __forceinline__ uint32_t pack2(float a, float b) {
    __nv_bfloat16 x = __float2bfloat16(a);
    __nv_bfloat16 y = __float2bfloat16(b);
    return (uint32_t)__bfloat16_as_ushort(x) | ((uint32_t)__bfloat16_as_ushort(y) << 16);
}
__device__ __forceinline__ void split_pack(float a, float b, uint32_t& hi, uint32_t& lo) {
    __nv_bfloat16 ah = __float2bfloat16(a);
    __nv_bfloat16 bh = __float2bfloat16(b);
    hi = (uint32_t)__bfloat16_as_ushort(ah) | ((uint32_t)__bfloat16_as_ushort(bh) << 16);
    lo = pack2(a - __bfloat162float(ah), b - __bfloat162float(bh));
}

// ---------------------------------------------------------------------------
// Weight transpose + bf16 hi/lo split; also concat qkv bias.
// ---------------------------------------------------------------------------
__global__ void convW(const float* __restrict__ Wq, const float* __restrict__ Wk,
                      const float* __restrict__ Wv, const float* __restrict__ Wp,
                      const float* __restrict__ bq, const float* __restrict__ bk,
                      const float* __restrict__ bv,
                      __nv_bfloat16* __restrict__ th, __nv_bfloat16* __restrict__ tl,
                      float* __restrict__ bqkv) {
    int idx = blockIdx.x * 256 + threadIdx.x;
    if (idx < 3 * 384)
        bqkv[idx] = (idx < 384) ? bq[idx] : (idx < 768) ? bk[idx - 384] : bv[idx - 768];
    if (idx >= 4 * 384 * 384) return;
    int m = idx / (384 * 384);
    int rem = idx - m * 384 * 384;
    int n = rem / 384, k = rem - (rem / 384) * 384;
    const float* W = (m == 0) ? Wq : (m == 1) ? Wk : (m == 2) ? Wv : Wp;
    float a = W[k * 384 + n];
    __nv_bfloat16 h = __float2bfloat16(a);
    th[idx] = h;
    tl[idx] = __float2bfloat16(a - __bfloat162float(h));
}

// ---------------------------------------------------------------------------
// x fp32 -> bf16 hi/lo
// ---------------------------------------------------------------------------
__global__ void convX(const float* __restrict__ x,
                      __nv_bfloat16* __restrict__ xh, __nv_bfloat16* __restrict__ xl) {
    size_t i = ((size_t)blockIdx.x * 256 + threadIdx.x) * 4;
    if (i >= (size_t)ROWS * DM) return;
    float4 v = *(const float4*)(x + i);
    uint32_t h0, l0, h1, l1;
    split_pack(v.x, v.y, h0, l0);
    split_pack(v.z, v.w, h1, l1);
    *(uint2*)(xh + i) = make_uint2(h0, h1);
    *(uint2*)(xl + i) = make_uint2(l0, l1);
}

// ---------------------------------------------------------------------------
// HMMA GEMM with cp.async 2-stage pipeline.
// MODE 1: proj  (all CTAs split, fp32 row-major out, B rows [0,384))
// MODE 2: qkv   (split iff bcol>=768; q,k -> bf16 g_qk; v -> bf16 hi/lo)
// ---------------------------------------------------------------------------
#define RB     80        // bytes per smem row (32 bf16 + 16B pad)
#define TILE_B 10240     // 128 * RB
#define STG_B  40960     // 4 tiles
#define T_AH   0
#define T_BH   10240
#define T_AL   20480
#define T_BL   30720
#define SMEM_GEMM 81920

template <int MODE>
__global__ __launch_bounds__(256, 2)
void gemm_cp(const __nv_bfloat16* __restrict__ Ah, const __nv_bfloat16* __restrict__ Al,
             const __nv_bfloat16* __restrict__ Bh, const __nv_bfloat16* __restrict__ Bl,
             const float* __restrict__ bias, float* __restrict__ Cbase) {
    extern __shared__ char smem[];
    const uint32_t sb = smem_u32(smem);
    const int tid = threadIdx.x;
    const int wid = tid >> 5, lane = tid & 31;
    const int warp_m = wid & 1, warp_n = wid >> 1;
    const int brow = blockIdx.y * 128;
    const int bcol = blockIdx.x * 128;
    const bool split = (MODE == 1) || (bcol >= 768);

    float acc[4][4][4];
#pragma unroll
    for (int i = 0; i < 4; i++)
#pragma unroll
        for (int j = 0; j < 4; j++)
#pragma unroll
            for (int c = 0; c < 4; c++) acc[i][j][c] = 0.f;

    const int r0 = tid >> 2, q0 = tid & 3;
    const int r1 = (tid + 256) >> 2, q1 = tid & 3;
    const size_t aoff0 = (size_t)(brow + r0) * DM + q0 * 8;
    const size_t aoff1 = (size_t)(brow + r1) * DM + q1 * 8;
    const size_t boff0 = (size_t)(bcol + r0) * DM + q0 * 8;
    const size_t boff1 = (size_t)(bcol + r1) * DM + q1 * 8;
    const uint32_t d0 = r0 * RB + q0 * 16;
    const uint32_t d1 = r1 * RB + q1 * 16;

    auto issue = [&](int kc, int s) {
        const uint32_t base = sb + s * STG_B;
        const int ko = kc * 32;
        cpa16(base + T_AH + d0, Ah + aoff0 + ko);
        cpa16(base + T_AH + d1, Ah + aoff1 + ko);
        cpa16(base + T_BH + d0, Bh + boff0 + ko);
        cpa16(base + T_BH + d1, Bh + boff1 + ko);
        if (split) {
            cpa16(base + T_AL + d0, Al + aoff0 + ko);
            cpa16(base + T_AL + d1, Al + aoff1 + ko);
            cpa16(base + T_BL + d0, Bl + boff0 + ko);
            cpa16(base + T_BL + d1, Bl + boff1 + ko);
        }
        CP_COMMIT();
    };

    const uint32_t a_off = (warp_m * 64 + (lane & 7) + ((lane >> 3) & 1) * 8) * RB
                         + ((lane >> 4) & 1) * 16;
    const uint32_t b_off = (warp_n * 32 + (lane & 7) + ((lane >> 4) & 1) * 8) * RB
                         + ((lane >> 3) & 1) * 16;

    issue(0, 0);

    for (int kc = 0; kc < 12; kc++) {
        if (kc < 11) {
            issue(kc + 1, (kc + 1) & 1);
            asm volatile("cp.async.wait_group 1;" ::: "memory");
        } else {
            asm volatile("cp.async.wait_group 0;" ::: "memory");
        }
        __syncthreads();

        const uint32_t base = sb + (kc & 1) * STG_B;
#pragma unroll
        for (int st = 0; st < 2; st++) {
            const uint32_t so = st * 32;
            uint32_t a[4][4], bh[4][2], bl[4][2];
#pragma unroll
            for (int mt = 0; mt < 4; mt++)
                ldsm4(a[mt][0], a[mt][1], a[mt][2], a[mt][3],
                      base + T_AH + a_off + mt * 16 * RB + so);
#pragma unroll
            for (int p = 0; p < 2; p++)
                ldsm4(bh[2 * p][0], bh[2 * p][1], bh[2 * p + 1][0], bh[2 * p + 1][1],
                      base + T_BH + b_off + p * 16 * RB + so);
#pragma unroll
            for (int mt = 0; mt < 4; mt++)
#pragma unroll
                for (int nt = 0; nt < 4; nt++)
                    mma16816(acc[mt][nt], a[mt], bh[nt]);

            if (split) {
#pragma unroll
                for (int p = 0; p < 2; p++)
                    ldsm4(bl[2 * p][0], bl[2 * p][1], bl[2 * p + 1][0], bl[2 * p + 1][1],
                          base + T_BL + b_off + p * 16 * RB + so);
#pragma unroll
                for (int mt = 0; mt < 4; mt++)
#pragma unroll
                    for (int nt = 0; nt < 4; nt++)
                        mma16816(acc[mt][nt], a[mt], bl[nt]);
#pragma unroll
                for (int mt = 0; mt < 4; mt++)
                    ldsm4(a[mt][0], a[mt][1], a[mt][2], a[mt][3],
                          base + T_AL + a_off + mt * 16 * RB + so);
#pragma unroll
                for (int mt = 0; mt < 4; mt++)
#pragma unroll
                    for (int nt = 0; nt < 4; nt++)
                        mma16816(acc[mt][nt], a[mt], bh[nt]);
            }
        }
        __syncthreads();
    }

    // epilogue
#pragma unroll
    for (int mt = 0; mt < 4; mt++) {
#pragma unroll
        for (int nt = 0; nt < 4; nt++) {
            const int gcol = bcol + warp_n * 32 + nt * 8 + (lane & 3) * 2;
            const float b0 = bias[gcol], b1 = bias[gcol + 1];
#pragma unroll
            for (int half = 0; half < 2; half++) {
                const int row = brow + warp_m * 64 + mt * 16 + (lane >> 2) + half * 8;
                float2 v;
                v.x = acc[mt][nt][half * 2 + 0] + b0;
                v.y = acc[mt][nt][half * 2 + 1] + b1;
                if (MODE == 1) {
                    *(float2*)(Cbase + (size_t)row * DM + gcol) = v;
                } else {
                    const int m = gcol / 384;
                    const int cm = gcol - m * 384;
                    const int hh = cm >> 5, dd = cm & 31;
                    const int bb2 = row / NTOK;
                    const int nn = row - bb2 * NTOK;
                    const size_t off = (((size_t)bb2 * NH + hh) * NTOK + nn) * HD + dd;
                    if (m < 2) {
                        *(uint32_t*)(g_qk + (size_t)m * ROWS * DM + off) = pack2(v.x, v.y);
                    } else {
                        uint32_t hh_, ll_;
                        split_pack(v.x, v.y, hh_, ll_);
                        *(uint32_t*)(g_vh + off) = hh_;
                        *(uint32_t*)(g_vl + off) = ll_;
                    }
                }
            }
        }
    }
}

// ---------------------------------------------------------------------------
// Tensor-core attention. CTA per (head h = blockIdx.x, window b = blockIdx.y),
// 128 threads = 4 warps; warp w handles output rows [16w, 16w+16).
// S = Q@K^T (bf16 mma, 49->64 pad); softmax fp32 in smem (overlays Q/K tiles);
// O = W@V via 3-term bf16 split (W frags built from fp32 smem via LDS+pack).
// ---------------------------------------------------------------------------
#define RB80     80
#define AOFF_Q   0
#define AOFF_K   5120
#define AOFF_VH  13056
#define AOFF_VL  18176
#define ATTN_SM  23296
#define SSW      66
#define SSF(r, c) sSf[(r) * SSW + (c)]

__global__ __launch_bounds__(128, 8)
void attn49(const __nv_bfloat16* __restrict__ qg, const __nv_bfloat16* __restrict__ kg,
            const __nv_bfloat16* __restrict__ vhg, const __nv_bfloat16* __restrict__ vlg,
            const float* __restrict__ mask,
            __nv_bfloat16* __restrict__ oh, __nv_bfloat16* __restrict__ ol) {
    __shared__ __align__(16) char smem[ATTN_SM];
    float* sSf = (float*)smem;
    const int h = blockIdx.x, b = blockIdx.y;
    const int tid = threadIdx.x, wid = tid >> 5, lane = tid & 31;
    const uint32_t sb = smem_u32(smem);
    const int m0 = wid * 16;

    // ---- load tiles (each tile is 49 rows x 64B, fully contiguous in gmem)
    {
        const size_t base = (((size_t)b * NH + h) * NTOK) * HD;
        const uint4* q4 = (const uint4*)(qg + base);
        const uint4* k4 = (const uint4*)(kg + base);
        const uint4* vh4 = (const uint4*)(vhg + base);
        const uint4* vl4 = (const uint4*)(vlg + base);
        for (int idx = tid; idx < NTOK * 4; idx += 128) {
            const int n = idx >> 2, c = idx & 3;
            const uint32_t d = n * RB80 + c * 16;
            *(uint4*)(smem + AOFF_Q + d) = q4[idx];
            *(uint4*)(smem + AOFF_K + d) = k4[idx];
            *(uint4*)(smem + AOFF_VH + d) = vh4[idx];
            *(uint4*)(smem + AOFF_VL + d) = vl4[idx];
        }
        // zero V pad rows 49..63 (first 64B) to avoid NaN propagation in MMA
        for (int idx = tid; idx < 120; idx += 128) {
            const int t = idx / 60;
            const int r = 49 + (idx % 60) / 4, c = idx & 3;
            const uint32_t d = r * RB80 + c * 16;
            *(uint4*)(smem + (t ? AOFF_VL : AOFF_VH) + d) = make_uint4(0, 0, 0, 0);
        }
    }
    __syncthreads();

    // ---- scores: S[64x64] via mma, per-warp 16 rows
    float c[8][4];
#pragma unroll
    for (int i = 0; i < 8; i++)
#pragma unroll
        for (int j = 0; j < 4; j++) c[i][j] = 0.f;
    {
        const uint32_t arow = (lane & 7) + ((lane >> 3) & 1) * 8;   // A pattern
        const uint32_t acb = ((lane >> 4) & 1) * 16;
        const uint32_t brow = (lane & 7) + ((lane >> 4) & 1) * 8;   // B pattern
        const uint32_t bcb = ((lane >> 3) & 1) * 16;
#pragma unroll
        for (int s = 0; s < 2; s++) {
            uint32_t a[4];
            ldsm4(a[0], a[1], a[2], a[3],
                  sb + AOFF_Q + (m0 + arow) * RB80 + acb + s * 32);
#pragma unroll
            for (int nb2 = 0; nb2 < 4; nb2++) {
                uint32_t bb_[4];
                ldsm4(bb_[0], bb_[1], bb_[2], bb_[3],
                      sb + AOFF_K + (nb2 * 16 + brow) * RB80 + bcb + s * 32);
                mma16816(c[2 * nb2], a, bb_);
                mma16816(c[2 * nb2 + 1], a, bb_ + 2);
            }
        }
    }
    __syncthreads();   // done reading sQ/sK; safe to overlay with sS

    // ---- write scores (scale + mask), zero pad cols
    {
        const float* mp = mask + (size_t)b * NTOK * NTOK;
        const int r0 = m0 + (lane >> 2);
        const int jc = 2 * (lane & 3);
#pragma unroll
        for (int nb = 0; nb < 8; nb++) {
            const int j0 = nb * 8 + jc;
            if (r0 < NTOK) {
                if (j0 < NTOK)     SSF(r0, j0)     = c[nb][0] * SCALE_F + mp[r0 * NTOK + j0];
                if (j0 + 1 < NTOK) SSF(r0, j0 + 1) = c[nb][1] * SCALE_F + mp[r0 * NTOK + j0 + 1];
            }
            if (r0 + 8 < NTOK) {
                if (j0 < NTOK)     SSF(r0 + 8, j0)     = c[nb][2] * SCALE_F + mp[(r0 + 8) * NTOK + j0];
                if (j0 + 1 < NTOK) SSF(r0 + 8, j0 + 1) = c[nb][3] * SCALE_F + mp[(r0 + 8) * NTOK + j0 + 1];
            }
        }
        for (int t = tid; t < NTOK * 17; t += 128)
            SSF(t / 17, 49 + t % 17) = 0.f;
    }
    __syncthreads();

    // ---- softmax: warp per row (rows 0..48)
    for (int r = wid; r < NTOK; r += 4) {
        float e0 = SSF(r, lane);
        float e1 = (lane + 32 < NTOK) ? SSF(r, lane + 32) : -3.4e38f;
        float m = fmaxf(e0, e1);
#pragma unroll
        for (int off = 16; off > 0; off >>= 1)
            m = fmaxf(m, __shfl_xor_sync(0xFFFFFFFFu, m, off));
        float x0 = __expf(e0 - m);
        float x1 = (lane + 32 < NTOK) ? __expf(e1 - m) : 0.f;
        float s = x0 + x1;
#pragma unroll
        for (int off = 16; off > 0; off >>= 1)
            s += __shfl_xor_sync(0xFFFFFFFFu, s, off);
        const float inv = 1.f / s;
        SSF(r, lane) = x0 * inv;
        if (lane + 32 < NTOK) SSF(r, lane + 32) = x1 * inv;
    }
    __syncthreads();

    // ---- O = W @ V (3-term split), per-warp 16 rows
    float acc[4][4];
#pragma unroll
    for (int i = 0; i < 4; i++)
#pragma unroll
        for (int j = 0; j < 4; j++) acc[i][j] = 0.f;
    {
        const uint32_t vrow = (lane & 7) + ((lane >> 3) & 1) * 8;   // trans-B pattern
        const uint32_t vcb = ((lane >> 4) & 1) * 16;
        const int ar0 = m0 + (lane >> 2);
        const int ar1 = ar0 + 8;
#pragma unroll
        for (int s = 0; s < 4; s++) {
            const int k0 = s * 16;
            const int ac = k0 + 2 * (lane & 3);
            float a00 = 0.f, a01 = 0.f, a20 = 0.f, a21 = 0.f;
            float a10 = 0.f, a11 = 0.f, a30 = 0.f, a31 = 0.f;
            if (ar0 < NTOK) {
                a00 = SSF(ar0, ac);     a01 = SSF(ar0, ac + 1);
                a20 = SSF(ar0, ac + 8); a21 = SSF(ar0, ac + 9);
            }
            if (ar1 < NTOK) {
                a10 = SSF(ar1, ac);     a11 = SSF(ar1, ac + 1);
                a30 = SSF(ar1, ac + 8); a31 = SSF(ar1, ac + 9);
            }
            uint32_t ah[4], al[4];
            split_pack(a00, a01, ah[0], al[0]);
            split_pack(a10, a11, ah[1], al[1]);
            split_pack(a20, a21, ah[2], al[2]);
            split_pack(a30, a31, ah[3], al[3]);
#pragma unroll
            for (int ch = 0; ch < 2; ch++) {
                uint32_t bvh[4], bvl[4];
                const uint32_t ba = (k0 + vrow) * RB80 + vcb + ch * 32;
                ldsm4t(bvh[0], bvh[1], bvh[2], bvh[3], sb + AOFF_VH + ba);
                ldsm4t(bvl[0], bvl[1], bvl[2], bvl[3], sb + AOFF_VL + ba);
                mma16816(acc[2 * ch], ah, bvh);
                mma16816(acc[2 * ch], ah, bvl);
                mma16816(acc[2 * ch], al, bvh);
                mma16816(acc[2 * ch + 1], ah, bvh + 2);
                mma16816(acc[2 * ch + 1], ah, bvl + 2);
                mma16816(acc[2 * ch + 1], al, bvh + 2);
            }
        }
    }

    // ---- store O as bf16 hi/lo
    {
        const int i0 = m0 + (lane >> 2), i1 = i0 + 8;
        const int dc = 2 * (lane & 3);
#pragma unroll
        for (int nb = 0; nb < 4; nb++) {
            const int d0 = nb * 8 + dc;
            if (i0 < NTOK) {
                uint32_t hh_, ll_;
                split_pack(acc[nb][0], acc[nb][1], hh_, ll_);
                const size_t off = ((size_t)b * NTOK + i0) * DM + h * HD + d0;
                *(uint32_t*)(oh + off) = hh_;
                *(uint32_t*)(ol + off) = ll_;
            }
            if (i1 < NTOK) {
                uint32_t hh_, ll_;
                split_pack(acc[nb][2], acc[nb][3], hh_, ll_);
                const size_t off = ((size_t)b * NTOK + i1) * DM + h * HD + d0;
                *(uint32_t*)(oh + off) = hh_;
                *(uint32_t*)(ol + off) = ll_;
            }
        }
    }
}

// ---------------------------------------------------------------------------
extern "C" void kernel_launch(void* const* d_in, const int* in_sizes, int n_in,
                              void* d_out, int out_size) {
    const float* x    = (const float*)d_in[0];
    const float* mask = (const float*)d_in[1];
    const float* Wq   = (const float*)d_in[2];
    const float* bq   = (const float*)d_in[3];
    const float* Wk   = (const float*)d_in[4];
    const float* bk   = (const float*)d_in[5];
    const float* Wv   = (const float*)d_in[6];
    const float* bv   = (const float*)d_in[7];
    const float* Wp   = (const float*)d_in[8];
    const float* bp   = (const float*)d_in[9];

    __nv_bfloat16 *xh, *xl, *oh, *ol, *wth, *wtl, *qk, *vh, *vl;
    float *bqkv;
    cudaGetSymbolAddress((void**)&xh, g_xh);
    cudaGetSymbolAddress((void**)&xl, g_xl);
    cudaGetSymbolAddress((void**)&oh, g_oh);
    cudaGetSymbolAddress((void**)&ol, g_ol);
    cudaGetSymbolAddress((void**)&wth, g_wth);
    cudaGetSymbolAddress((void**)&wtl, g_wtl);
    cudaGetSymbolAddress((void**)&qk, g_qk);
    cudaGetSymbolAddress((void**)&vh, g_vh);
    cudaGetSymbolAddress((void**)&vl, g_vl);
    cudaGetSymbolAddress((void**)&bqkv, g_bqkv);

    cudaFuncSetAttribute(gemm_cp<1>, cudaFuncAttributeMaxDynamicSharedMemorySize, SMEM_GEMM);
    cudaFuncSetAttribute(gemm_cp<2>, cudaFuncAttributeMaxDynamicSharedMemorySize, SMEM_GEMM);

    convW<<<(4 * 384 * 384 + 255) / 256, 256>>>(Wq, Wk, Wv, Wp, bq, bk, bv, wth, wtl, bqkv);
    convX<<<(int)(((size_t)ROWS * DM / 4 + 255) / 256), 256>>>(x, xh, xl);

    dim3 qkvgrid(9, ROWS / 128);
    gemm_cp<2><<<qkvgrid, 256, SMEM_GEMM>>>(xh, xl, wth, wtl, bqkv, (float*)d_out);

    dim3 agrid(NH, NWIN);
    attn49<<<agrid, 128>>>(qk, qk + (size_t)ROWS * DM, vh, vl, mask, oh, ol);

    dim3 pgrid(3, ROWS / 128);
    gemm_cp<1><<<pgrid, 256, SMEM_GEMM>>>(oh, ol, wth + 3 * 147456, wtl + 3 * 147456,
                                          bp, (float*)d_out);
}

// round 7
// speedup vs baseline: 6.4474x; 1.1535x over previous
#include <cuda_runtime.h>
#include <cuda_bf16.h>
#include <cstdint>
#include <math.h>

#define ROWS 200704   // 4096 * 49
#define DM   384
#define NWIN 4096
#define NH   12
#define NTOK 49
#define HD   32

// SCALE = 32^-5 (faithful to reference code)
#define SCALE_F 2.9802322387695312e-08f

// ---------------------------------------------------------------------------
// Scratch (__device__ globals; no allocation allowed)
// ---------------------------------------------------------------------------
__device__ __nv_bfloat16 g_xh[(size_t)ROWS * DM];
__device__ __nv_bfloat16 g_xl[(size_t)ROWS * DM];
__device__ __nv_bfloat16 g_qk[(size_t)2 * ROWS * DM];    // q,k head-split bf16
__device__ __nv_bfloat16 g_vh[(size_t)ROWS * DM];        // v head-split hi
__device__ __nv_bfloat16 g_vl[(size_t)ROWS * DM];        // v head-split lo
__device__ __nv_bfloat16 g_oh[(size_t)ROWS * DM];        // attn out hi
__device__ __nv_bfloat16 g_ol[(size_t)ROWS * DM];        // attn out lo
__device__ __nv_bfloat16 g_wth[4 * 384 * 384];           // W^T hi [m][n][k]
__device__ __nv_bfloat16 g_wtl[4 * 384 * 384];           // W^T lo
__device__ float         g_bqkv[3 * 384];                // concat bq,bk,bv

// ---------------------------------------------------------------------------
__device__ __forceinline__ uint32_t smem_u32(const void* p) {
    uint32_t a;
    asm("{ .reg .u64 t; cvta.to.shared.u64 t, %1; cvt.u32.u64 %0, t; }" : "=r"(a) : "l"(p));
    return a;
}
__device__ __forceinline__ void ldsm4(uint32_t& r0, uint32_t& r1, uint32_t& r2, uint32_t& r3,
                                      uint32_t addr) {
    asm volatile("ldmatrix.sync.aligned.m8n8.x4.shared.b16 {%0,%1,%2,%3}, [%4];"
                 : "=r"(r0), "=r"(r1), "=r"(r2), "=r"(r3) : "r"(addr));
}
__device__ __forceinline__ void ldsm4t(uint32_t& r0, uint32_t& r1, uint32_t& r2, uint32_t& r3,
                                       uint32_t addr) {
    asm volatile("ldmatrix.sync.aligned.m8n8.x4.trans.shared.b16 {%0,%1,%2,%3}, [%4];"
                 : "=r"(r0), "=r"(r1), "=r"(r2), "=r"(r3) : "r"(addr));
}
__device__ __forceinline__ void mma16816(float* d, const uint32_t* a, const uint32_t* b) {
    asm volatile("mma.sync.aligned.m16n8k16.row.col.f32.bf16.bf16.f32 "
                 "{%0,%1,%2,%3}, {%4,%5,%6,%7}, {%8,%9}, {%0,%1,%2,%3};"
                 : "+f"(d[0]), "+f"(d[1]), "+f"(d[2]), "+f"(d[3])
                 : "r"(a[0]), "r"(a[1]), "r"(a[2]), "r"(a[3]), "r"(b[0]), "r"(b[1]));
}
__device__ __forceinline__ void cpa16(uint32_t dst, const void* src) {
    asm volatile("cp.async.cg.shared.global [%0], [%1], 16;" :: "r"(dst), "l"(src));
}
#define CP_COMMIT() asm volatile("cp.async.commit_group;" ::: "memory")

__device__ __forceinline__ uint32_t pack2(float a, float b) {
    __nv_bfloat16 x = __float2bfloat16(a);
    __nv_bfloat16 y = __float2bfloat16(b);
    return (uint32_t)__bfloat16_as_ushort(x) | ((uint32_t)__bfloat16_as_ushort(y) << 16);
}
__device__ __forceinline__ void split_pack(float a, float b, uint32_t& hi, uint32_t& lo) {
    __nv_bfloat16 ah = __float2bfloat16(a);
    __nv_bfloat16 bh = __float2bfloat16(b);
    hi = (uint32_t)__bfloat16_as_ushort(ah) | ((uint32_t)__bfloat16_as_ushort(bh) << 16);
    lo = pack2(a - __bfloat162float(ah), b - __bfloat162float(bh));
}

// ---------------------------------------------------------------------------
// Weight transpose + bf16 hi/lo split; also concat qkv bias.
// ---------------------------------------------------------------------------
__global__ void convW(const float* __restrict__ Wq, const float* __restrict__ Wk,
                      const float* __restrict__ Wv, const float* __restrict__ Wp,
                      const float* __restrict__ bq, const float* __restrict__ bk,
                      const float* __restrict__ bv,
                      __nv_bfloat16* __restrict__ th, __nv_bfloat16* __restrict__ tl,
                      float* __restrict__ bqkv) {
    int idx = blockIdx.x * 256 + threadIdx.x;
    if (idx < 3 * 384)
        bqkv[idx] = (idx < 384) ? bq[idx] : (idx < 768) ? bk[idx - 384] : bv[idx - 768];
    if (idx >= 4 * 384 * 384) return;
    int m = idx / (384 * 384);
    int rem = idx - m * 384 * 384;
    int n = rem / 384, k = rem - (rem / 384) * 384;
    const float* W = (m == 0) ? Wq : (m == 1) ? Wk : (m == 2) ? Wv : Wp;
    float a = W[k * 384 + n];
    __nv_bfloat16 h = __float2bfloat16(a);
    th[idx] = h;
    tl[idx] = __float2bfloat16(a - __bfloat162float(h));
}

// ---------------------------------------------------------------------------
// x fp32 -> bf16 hi/lo
// ---------------------------------------------------------------------------
__global__ void convX(const float* __restrict__ x,
                      __nv_bfloat16* __restrict__ xh, __nv_bfloat16* __restrict__ xl) {
    size_t i = ((size_t)blockIdx.x * 256 + threadIdx.x) * 4;
    if (i >= (size_t)ROWS * DM) return;
    float4 v = *(const float4*)(x + i);
    uint32_t h0, l0, h1, l1;
    split_pack(v.x, v.y, h0, l0);
    split_pack(v.z, v.w, h1, l1);
    *(uint2*)(xh + i) = make_uint2(h0, h1);
    *(uint2*)(xl + i) = make_uint2(l0, l1);
}

// ---------------------------------------------------------------------------
// HMMA GEMM with cp.async 2-stage pipeline.
// MODE 1: proj  (all CTAs split, fp32 row-major out, B rows [0,384))
// MODE 2: qkv   (split iff bcol>=768; q,k -> bf16 g_qk; v -> bf16 hi/lo)
// ---------------------------------------------------------------------------
#define RB     80        // bytes per smem row (32 bf16 + 16B pad)
#define TILE_B 10240     // 128 * RB
#define STG_B  40960     // 4 tiles
#define T_AH   0
#define T_BH   10240
#define T_AL   20480
#define T_BL   30720
#define SMEM_GEMM 81920

template <int MODE>
__global__ __launch_bounds__(256, 2)
void gemm_cp(const __nv_bfloat16* __restrict__ Ah, const __nv_bfloat16* __restrict__ Al,
             const __nv_bfloat16* __restrict__ Bh, const __nv_bfloat16* __restrict__ Bl,
             const float* __restrict__ bias, float* __restrict__ Cbase) {
    extern __shared__ char smem[];
    const uint32_t sb = smem_u32(smem);
    const int tid = threadIdx.x;
    const int wid = tid >> 5, lane = tid & 31;
    const int warp_m = wid & 1, warp_n = wid >> 1;
    const int brow = blockIdx.y * 128;
    const int bcol = blockIdx.x * 128;
    const bool split = (MODE == 1) || (bcol >= 768);

    float acc[4][4][4];
#pragma unroll
    for (int i = 0; i < 4; i++)
#pragma unroll
        for (int j = 0; j < 4; j++)
#pragma unroll
            for (int c = 0; c < 4; c++) acc[i][j][c] = 0.f;

    const int r0 = tid >> 2, q0 = tid & 3;
    const int r1 = (tid + 256) >> 2, q1 = tid & 3;
    const size_t aoff0 = (size_t)(brow + r0) * DM + q0 * 8;
    const size_t aoff1 = (size_t)(brow + r1) * DM + q1 * 8;
    const size_t boff0 = (size_t)(bcol + r0) * DM + q0 * 8;
    const size_t boff1 = (size_t)(bcol + r1) * DM + q1 * 8;
    const uint32_t d0 = r0 * RB + q0 * 16;
    const uint32_t d1 = r1 * RB + q1 * 16;

    auto issue = [&](int kc, int s) {
        const uint32_t base = sb + s * STG_B;
        const int ko = kc * 32;
        cpa16(base + T_AH + d0, Ah + aoff0 + ko);
        cpa16(base + T_AH + d1, Ah + aoff1 + ko);
        cpa16(base + T_BH + d0, Bh + boff0 + ko);
        cpa16(base + T_BH + d1, Bh + boff1 + ko);
        if (split) {
            cpa16(base + T_AL + d0, Al + aoff0 + ko);
            cpa16(base + T_AL + d1, Al + aoff1 + ko);
            cpa16(base + T_BL + d0, Bl + boff0 + ko);
            cpa16(base + T_BL + d1, Bl + boff1 + ko);
        }
        CP_COMMIT();
    };

    const uint32_t a_off = (warp_m * 64 + (lane & 7) + ((lane >> 3) & 1) * 8) * RB
                         + ((lane >> 4) & 1) * 16;
    const uint32_t b_off = (warp_n * 32 + (lane & 7) + ((lane >> 4) & 1) * 8) * RB
                         + ((lane >> 3) & 1) * 16;

    issue(0, 0);

    for (int kc = 0; kc < 12; kc++) {
        if (kc < 11) {
            issue(kc + 1, (kc + 1) & 1);
            asm volatile("cp.async.wait_group 1;" ::: "memory");
        } else {
            asm volatile("cp.async.wait_group 0;" ::: "memory");
        }
        __syncthreads();

        const uint32_t base = sb + (kc & 1) * STG_B;
#pragma unroll
        for (int st = 0; st < 2; st++) {
            const uint32_t so = st * 32;
            uint32_t a[4][4], bh[4][2], bl[4][2];
#pragma unroll
            for (int mt = 0; mt < 4; mt++)
                ldsm4(a[mt][0], a[mt][1], a[mt][2], a[mt][3],
                      base + T_AH + a_off + mt * 16 * RB + so);
#pragma unroll
            for (int p = 0; p < 2; p++)
                ldsm4(bh[2 * p][0], bh[2 * p][1], bh[2 * p + 1][0], bh[2 * p + 1][1],
                      base + T_BH + b_off + p * 16 * RB + so);
#pragma unroll
            for (int mt = 0; mt < 4; mt++)
#pragma unroll
                for (int nt = 0; nt < 4; nt++)
                    mma16816(acc[mt][nt], a[mt], bh[nt]);

            if (split) {
#pragma unroll
                for (int p = 0; p < 2; p++)
                    ldsm4(bl[2 * p][0], bl[2 * p][1], bl[2 * p + 1][0], bl[2 * p + 1][1],
                          base + T_BL + b_off + p * 16 * RB + so);
#pragma unroll
                for (int mt = 0; mt < 4; mt++)
#pragma unroll
                    for (int nt = 0; nt < 4; nt++)
                        mma16816(acc[mt][nt], a[mt], bl[nt]);
#pragma unroll
                for (int mt = 0; mt < 4; mt++)
                    ldsm4(a[mt][0], a[mt][1], a[mt][2], a[mt][3],
                          base + T_AL + a_off + mt * 16 * RB + so);
#pragma unroll
                for (int mt = 0; mt < 4; mt++)
#pragma unroll
                    for (int nt = 0; nt < 4; nt++)
                        mma16816(acc[mt][nt], a[mt], bh[nt]);
            }
        }
        __syncthreads();
    }

    // epilogue
#pragma unroll
    for (int mt = 0; mt < 4; mt++) {
#pragma unroll
        for (int nt = 0; nt < 4; nt++) {
            const int gcol = bcol + warp_n * 32 + nt * 8 + (lane & 3) * 2;
            const float b0 = bias[gcol], b1 = bias[gcol + 1];
#pragma unroll
            for (int half = 0; half < 2; half++) {
                const int row = brow + warp_m * 64 + mt * 16 + (lane >> 2) + half * 8;
                float2 v;
                v.x = acc[mt][nt][half * 2 + 0] + b0;
                v.y = acc[mt][nt][half * 2 + 1] + b1;
                if (MODE == 1) {
                    *(float2*)(Cbase + (size_t)row * DM + gcol) = v;
                } else {
                    const int m = gcol / 384;
                    const int cm = gcol - m * 384;
                    const int hh = cm >> 5, dd = cm & 31;
                    const int bb2 = row / NTOK;
                    const int nn = row - bb2 * NTOK;
                    const size_t off = (((size_t)bb2 * NH + hh) * NTOK + nn) * HD + dd;
                    if (m < 2) {
                        *(uint32_t*)(g_qk + (size_t)m * ROWS * DM + off) = pack2(v.x, v.y);
                    } else {
                        uint32_t hh_, ll_;
                        split_pack(v.x, v.y, hh_, ll_);
                        *(uint32_t*)(g_vh + off) = hh_;
                        *(uint32_t*)(g_vl + off) = ll_;
                    }
                }
            }
        }
    }
}

// ---------------------------------------------------------------------------
// Tensor-core attention, register-resident softmax.
// CTA per (head h = blockIdx.x, window b = blockIdx.y), 4 warps;
// warp w owns output rows [16w, 16w+16).
// S frags (C layout) are reused directly as A frags for O = W@V.
// ---------------------------------------------------------------------------
#define RB80     80
#define AOFF_Q   0        // 64 rows x 80B
#define AOFF_K   5120
#define AOFF_VH  10240
#define AOFF_VL  15360
#define ATTN_SM  20480

__global__ __launch_bounds__(128, 6)
void attn49(const __nv_bfloat16* __restrict__ qg, const __nv_bfloat16* __restrict__ kg,
            const __nv_bfloat16* __restrict__ vhg, const __nv_bfloat16* __restrict__ vlg,
            const float* __restrict__ mask,
            __nv_bfloat16* __restrict__ oh, __nv_bfloat16* __restrict__ ol) {
    __shared__ __align__(16) char smem[ATTN_SM];
    const int h = blockIdx.x, b = blockIdx.y;
    const int tid = threadIdx.x, wid = tid >> 5, lane = tid & 31;
    const uint32_t sb = smem_u32(smem);
    const int m0 = wid * 16;

    // ---- load tiles (49 rows x 64B each, contiguous in gmem)
    {
        const size_t base = (((size_t)b * NH + h) * NTOK) * HD;
        const uint4* q4 = (const uint4*)(qg + base);
        const uint4* k4 = (const uint4*)(kg + base);
        const uint4* vh4 = (const uint4*)(vhg + base);
        const uint4* vl4 = (const uint4*)(vlg + base);
        for (int idx = tid; idx < NTOK * 4; idx += 128) {
            const int n = idx >> 2, c = idx & 3;
            const uint32_t d = n * RB80 + c * 16;
            *(uint4*)(smem + AOFF_Q + d) = q4[idx];
            *(uint4*)(smem + AOFF_K + d) = k4[idx];
            *(uint4*)(smem + AOFF_VH + d) = vh4[idx];
            *(uint4*)(smem + AOFF_VL + d) = vl4[idx];
        }
        // zero V pad rows 49..63 (avoid NaN x 0 in O mma)
        for (int idx = tid; idx < 120; idx += 128) {
            const int t = idx / 60;
            const int r = 49 + (idx % 60) / 4, c = idx & 3;
            const uint32_t d = r * RB80 + c * 16;
            *(uint4*)(smem + (t ? AOFF_VL : AOFF_VH) + d) = make_uint4(0, 0, 0, 0);
        }
    }
    __syncthreads();

    // ---- S = Q @ K^T into registers c[8][4]
    float c[8][4];
#pragma unroll
    for (int i = 0; i < 8; i++)
#pragma unroll
        for (int j = 0; j < 4; j++) c[i][j] = 0.f;
    {
        const uint32_t arow = (lane & 7) + ((lane >> 3) & 1) * 8;
        const uint32_t acb = ((lane >> 4) & 1) * 16;
        const uint32_t brow = (lane & 7) + ((lane >> 4) & 1) * 8;
        const uint32_t bcb = ((lane >> 3) & 1) * 16;
#pragma unroll
        for (int s = 0; s < 2; s++) {
            uint32_t a[4];
            ldsm4(a[0], a[1], a[2], a[3],
                  sb + AOFF_Q + (m0 + arow) * RB80 + acb + s * 32);
#pragma unroll
            for (int nb2 = 0; nb2 < 4; nb2++) {
                uint32_t bb_[4];
                ldsm4(bb_[0], bb_[1], bb_[2], bb_[3],
                      sb + AOFF_K + (nb2 * 16 + brow) * RB80 + bcb + s * 32);
                mma16816(c[2 * nb2], a, bb_);
                mma16816(c[2 * nb2 + 1], a, bb_ + 2);
            }
        }
    }

    // ---- scale + mask + pad handling, all in registers
    const int r0 = m0 + (lane >> 2);
    const int r1 = r0 + 8;
    const int jc = 2 * (lane & 3);
    const bool v0 = (r0 < NTOK), v1 = (r1 < NTOK);
    {
        const float* mp = mask + (size_t)b * NTOK * NTOK;
#pragma unroll
        for (int nb = 0; nb < 8; nb++) {
            const int jA = nb * 8 + jc, jB = jA + 1;
            const bool ja = (jA < NTOK), jb_ = (jB < NTOK);
            c[nb][0] = (v0 && ja)  ? c[nb][0] * SCALE_F + __ldg(mp + r0 * NTOK + jA) : (v0 ? -1e30f : 0.f);
            c[nb][1] = (v0 && jb_) ? c[nb][1] * SCALE_F + __ldg(mp + r0 * NTOK + jB) : (v0 ? -1e30f : 0.f);
            c[nb][2] = (v1 && ja)  ? c[nb][2] * SCALE_F + __ldg(mp + r1 * NTOK + jA) : (v1 ? -1e30f : 0.f);
            c[nb][3] = (v1 && jb_) ? c[nb][3] * SCALE_F + __ldg(mp + r1 * NTOK + jB) : (v1 ? -1e30f : 0.f);
        }
    }

    // ---- softmax: quad (4 lanes) owns each row
    {
        float m0f = -1e30f, m1f = -1e30f;
#pragma unroll
        for (int nb = 0; nb < 8; nb++) {
            m0f = fmaxf(m0f, fmaxf(c[nb][0], c[nb][1]));
            m1f = fmaxf(m1f, fmaxf(c[nb][2], c[nb][3]));
        }
        m0f = fmaxf(m0f, __shfl_xor_sync(0xFFFFFFFFu, m0f, 1));
        m0f = fmaxf(m0f, __shfl_xor_sync(0xFFFFFFFFu, m0f, 2));
        m1f = fmaxf(m1f, __shfl_xor_sync(0xFFFFFFFFu, m1f, 1));
        m1f = fmaxf(m1f, __shfl_xor_sync(0xFFFFFFFFu, m1f, 2));
        float s0 = 0.f, s1 = 0.f;
#pragma unroll
        for (int nb = 0; nb < 8; nb++) {
            c[nb][0] = __expf(c[nb][0] - m0f);
            c[nb][1] = __expf(c[nb][1] - m0f);
            c[nb][2] = __expf(c[nb][2] - m1f);
            c[nb][3] = __expf(c[nb][3] - m1f);
            s0 += c[nb][0] + c[nb][1];
            s1 += c[nb][2] + c[nb][3];
        }
        s0 += __shfl_xor_sync(0xFFFFFFFFu, s0, 1);
        s0 += __shfl_xor_sync(0xFFFFFFFFu, s0, 2);
        s1 += __shfl_xor_sync(0xFFFFFFFFu, s1, 1);
        s1 += __shfl_xor_sync(0xFFFFFFFFu, s1, 2);
        const float i0 = 1.f / s0, i1 = 1.f / s1;
#pragma unroll
        for (int nb = 0; nb < 8; nb++) {
            c[nb][0] *= i0; c[nb][1] *= i0;
            c[nb][2] *= i1; c[nb][3] *= i1;
        }
    }

    // ---- O = W @ V (3-term split); A frags packed straight from c[][]
    float acc[4][4];
#pragma unroll
    for (int i = 0; i < 4; i++)
#pragma unroll
        for (int j = 0; j < 4; j++) acc[i][j] = 0.f;
    {
        const uint32_t vrow = (lane & 7) + ((lane >> 3) & 1) * 8;
        const uint32_t vcb = ((lane >> 4) & 1) * 16;
#pragma unroll
        for (int s = 0; s < 4; s++) {
            uint32_t ah[4], al[4];
            split_pack(c[2 * s][0],     c[2 * s][1],     ah[0], al[0]);
            split_pack(c[2 * s][2],     c[2 * s][3],     ah[1], al[1]);
            split_pack(c[2 * s + 1][0], c[2 * s + 1][1], ah[2], al[2]);
            split_pack(c[2 * s + 1][2], c[2 * s + 1][3], ah[3], al[3]);
#pragma unroll
            for (int ch = 0; ch < 2; ch++) {
                uint32_t bvh[4], bvl[4];
                const uint32_t ba = (s * 16 + vrow) * RB80 + vcb + ch * 32;
                ldsm4t(bvh[0], bvh[1], bvh[2], bvh[3], sb + AOFF_VH + ba);
                ldsm4t(bvl[0], bvl[1], bvl[2], bvl[3], sb + AOFF_VL + ba);
                mma16816(acc[2 * ch], ah, bvh);
                mma16816(acc[2 * ch], ah, bvl);
                mma16816(acc[2 * ch], al, bvh);
                mma16816(acc[2 * ch + 1], ah, bvh + 2);
                mma16816(acc[2 * ch + 1], ah, bvl + 2);
                mma16816(acc[2 * ch + 1], al, bvh + 2);
            }
        }
    }

    // ---- store O as bf16 hi/lo
    {
#pragma unroll
        for (int nb = 0; nb < 4; nb++) {
            const int d0 = nb * 8 + jc;
            if (v0) {
                uint32_t hh_, ll_;
                split_pack(acc[nb][0], acc[nb][1], hh_, ll_);
                const size_t off = ((size_t)b * NTOK + r0) * DM + h * HD + d0;
                *(uint32_t*)(oh + off) = hh_;
                *(uint32_t*)(ol + off) = ll_;
            }
            if (v1) {
                uint32_t hh_, ll_;
                split_pack(acc[nb][2], acc[nb][3], hh_, ll_);
                const size_t off = ((size_t)b * NTOK + r1) * DM + h * HD + d0;
                *(uint32_t*)(oh + off) = hh_;
                *(uint32_t*)(ol + off) = ll_;
            }
        }
    }
}

// ---------------------------------------------------------------------------
extern "C" void kernel_launch(void* const* d_in, const int* in_sizes, int n_in,
                              void* d_out, int out_size) {
    const float* x    = (const float*)d_in[0];
    const float* mask = (const float*)d_in[1];
    const float* Wq   = (const float*)d_in[2];
    const float* bq   = (const float*)d_in[3];
    const float* Wk   = (const float*)d_in[4];
    const float* bk   = (const float*)d_in[5];
    const float* Wv   = (const float*)d_in[6];
    const float* bv   = (const float*)d_in[7];
    const float* Wp   = (const float*)d_in[8];
    const float* bp   = (const float*)d_in[9];

    __nv_bfloat16 *xh, *xl, *oh, *ol, *wth, *wtl, *qk, *vh, *vl;
    float *bqkv;
    cudaGetSymbolAddress((void**)&xh, g_xh);
    cudaGetSymbolAddress((void**)&xl, g_xl);
    cudaGetSymbolAddress((void**)&oh, g_oh);
    cudaGetSymbolAddress((void**)&ol, g_ol);
    cudaGetSymbolAddress((void**)&wth, g_wth);
    cudaGetSymbolAddress((void**)&wtl, g_wtl);
    cudaGetSymbolAddress((void**)&qk, g_qk);
    cudaGetSymbolAddress((void**)&vh, g_vh);
    cudaGetSymbolAddress((void**)&vl, g_vl);
    cudaGetSymbolAddress((void**)&bqkv, g_bqkv);

    cudaFuncSetAttribute(gemm_cp<1>, cudaFuncAttributeMaxDynamicSharedMemorySize, SMEM_GEMM);
    cudaFuncSetAttribute(gemm_cp<2>, cudaFuncAttributeMaxDynamicSharedMemorySize, SMEM_GEMM);

    convW<<<(4 * 384 * 384 + 255) / 256, 256>>>(Wq, Wk, Wv, Wp, bq, bk, bv, wth, wtl, bqkv);
    convX<<<(int)(((size_t)ROWS * DM / 4 + 255) / 256), 256>>>(x, xh, xl);

    dim3 qkvgrid(9, ROWS / 128);
    gemm_cp<2><<<qkvgrid, 256, SMEM_GEMM>>>(xh, xl, wth, wtl, bqkv, (float*)d_out);

    dim3 agrid(NH, NWIN);
    attn49<<<agrid, 128>>>(qk, qk + (size_t)ROWS * DM, vh, vl, mask, oh, ol);

    dim3 pgrid(3, ROWS / 128);
    gemm_cp<1><<<pgrid, 256, SMEM_GEMM>>>(oh, ol, wth + 3 * 147456, wtl + 3 * 147456,
                                          bp, (float*)d_out);
}